// round 11
// baseline (speedup 1.0000x reference)
#include <cuda_runtime.h>
#include <math.h>
#include <stdint.h>

#define F   256
#define NG  1024

// GEMM tile config (GH/proj): BM=BN=64, BK=16, TM=TN=4, 256 threads
#define BM 64
#define BN 64
#define BK 16

#define GH_BX 16                  // 1024/64
#define GH_BY 12                  // 768/64
#define GH_BLOCKS (GH_BX * GH_BY) // 192

// ---------------- scratch ----------------
__device__ float g_wf[NG * F];
__device__ int   g_cnt[NG];
__device__ float g_x[NG * F];
__device__ float g_gi[NG * 3 * F];
__device__ float g_gh[NG * 3 * F];

// ---------------- f32x2 packed-math helpers ----------------
__device__ __forceinline__ uint64_t pack2(float x, float y) {
    uint64_t r; asm("mov.b64 %0, {%1, %2};" : "=l"(r) : "f"(x), "f"(y)); return r;
}
__device__ __forceinline__ uint64_t bcast2(float x) {
    uint64_t r; asm("mov.b64 %0, {%1, %1};" : "=l"(r) : "f"(x)); return r;
}
__device__ __forceinline__ void ffma2(uint64_t& d, uint64_t a, uint64_t b) {
    asm("fma.rn.f32x2 %0, %1, %2, %0;" : "+l"(d) : "l"(a), "l"(b));
}
__device__ __forceinline__ float2 unpack2(uint64_t v) {
    float2 f; asm("mov.b64 {%0, %1}, %2;" : "=f"(f.x), "=f"(f.y) : "l"(v)); return f;
}
__device__ __forceinline__ float fast_tanh(float x) {
    float r; asm("tanh.approx.f32 %0, %1;" : "=f"(r) : "f"(x)); return r;
}
__device__ __forceinline__ float4 ldcs4(const float4* p) {
    float4 v;
    asm("ld.global.cs.v4.f32 {%0,%1,%2,%3}, [%4];"
        : "=f"(v.x), "=f"(v.y), "=f"(v.z), "=f"(v.w) : "l"(p));
    return v;
}

// ---------------- shared memory layouts ----------------
struct SmemGemm {
    float As[2][BK][BM + 4];
    float Ws[2][BK][BN + 4];
};
struct SmemPool {
    float red[8];
    float c;
    float s[8];
    int   bnd[2];
    float acc[8][F];
};
union SmemU { SmemGemm g; SmemPool p; };

// ---------------- GEMM body: C[M,N] = A[M,K] @ W[N,K]^T + bias ----------------
template <int EPI>
__device__ __forceinline__ void gemm_body(
    SmemGemm& S,
    const float* __restrict__ A, const float* __restrict__ W,
    const float* __restrict__ bias, float* __restrict__ C,
    const int* __restrict__ cnt, int N, int K, int bx, int by)
{
    const int tid  = threadIdx.x;
    const int tx   = tid % (BN / 4);
    const int ty   = tid / (BN / 4);
    const int row0 = bx * BM;
    const int col0 = by * BN;

    float4 aR, wR;
    const int r_ld  = tid / (BK / 4);
    const int c4_ld = tid % (BK / 4);

    auto ldg = [&](int k0) {
        aR = *reinterpret_cast<const float4*>(A + (size_t)(row0 + r_ld) * K + k0 + c4_ld * 4);
        wR = *reinterpret_cast<const float4*>(W + (size_t)(col0 + r_ld) * K + k0 + c4_ld * 4);
    };
    auto sts = [&](int buf) {
        S.As[buf][c4_ld * 4 + 0][r_ld] = aR.x;
        S.As[buf][c4_ld * 4 + 1][r_ld] = aR.y;
        S.As[buf][c4_ld * 4 + 2][r_ld] = aR.z;
        S.As[buf][c4_ld * 4 + 3][r_ld] = aR.w;
        S.Ws[buf][c4_ld * 4 + 0][r_ld] = wR.x;
        S.Ws[buf][c4_ld * 4 + 1][r_ld] = wR.y;
        S.Ws[buf][c4_ld * 4 + 2][r_ld] = wR.z;
        S.Ws[buf][c4_ld * 4 + 3][r_ld] = wR.w;
    };

    uint64_t acc2[4][2];
    #pragma unroll
    for (int i = 0; i < 4; ++i) { acc2[i][0] = 0ull; acc2[i][1] = 0ull; }

    const int T = K / BK;
    ldg(0);
    sts(0);
    __syncthreads();

    for (int t = 0; t < T; ++t) {
        if (t + 1 < T) ldg((t + 1) * BK);
        const int buf = t & 1;
        #pragma unroll
        for (int kk = 0; kk < BK; ++kk) {
            float4 ra = *reinterpret_cast<const float4*>(&S.As[buf][kk][ty * 4]);
            float4 rw = *reinterpret_cast<const float4*>(&S.Ws[buf][kk][tx * 4]);
            uint64_t b01 = pack2(rw.x, rw.y);
            uint64_t b23 = pack2(rw.z, rw.w);
            uint64_t a0 = bcast2(ra.x), a1 = bcast2(ra.y);
            uint64_t a2 = bcast2(ra.z), a3 = bcast2(ra.w);
            ffma2(acc2[0][0], a0, b01); ffma2(acc2[0][1], a0, b23);
            ffma2(acc2[1][0], a1, b01); ffma2(acc2[1][1], a1, b23);
            ffma2(acc2[2][0], a2, b01); ffma2(acc2[2][1], a2, b23);
            ffma2(acc2[3][0], a3, b01); ffma2(acc2[3][1], a3, b23);
        }
        if (t + 1 < T) {
            sts((t + 1) & 1);
            __syncthreads();
        }
    }

    #pragma unroll
    for (int i = 0; i < 4; ++i) {
        int r = row0 + ty * 4 + i;
        int cz = (EPI == 1) ? cnt[r] : 1;
        #pragma unroll
        for (int j = 0; j < 2; ++j) {
            int col = col0 + tx * 4 + j * 2;
            float2 v = unpack2(acc2[i][j]);
            v.x += bias[col];
            v.y += bias[col + 1];
            if (EPI == 1) {
                v.x = v.x > 0.f ? v.x : expm1f(v.x);
                v.y = v.y > 0.f ? v.y : expm1f(v.y);
                if (cz == 0) { v.x = 0.f; v.y = 0.f; }
            }
            *reinterpret_cast<float2*>(C + (size_t)r * N + col) = v;
        }
    }
}

// ---------------- binary search (segment_ids sorted) ----------------
__device__ __forceinline__ int lbound(const int* __restrict__ seg, int n, int key) {
    int lo = 0, hi = n;
    while (lo < hi) {
        int mid = (lo + hi) >> 1;
        if (__ldg(seg + mid) < key) lo = mid + 1; else hi = mid;
    }
    return lo;
}

// ---------------- fused: GH GEMM blocks + pool blocks ----------------
// Pool: unnormalized exp accumulation, coalesced lanes, UNROLL-3 with 6
// front-batched contiguous LDG.128. launch_bounds(256,4) -> regs<=64 ->
// 4 blocks (32 warps)/SM. Chip-wide outstanding loads stay equal to the
// unroll-4/3-block config while extra warps hide the math phase.
__global__ void __launch_bounds__(256, 4) fused_pool_gh_kernel(
    const float* __restrict__ nf, const float* __restrict__ gf,
    const float* __restrict__ lw, const float* __restrict__ lb,
    const float* __restrict__ whh, const float* __restrict__ bhh,
    const int* __restrict__ seg, int n_nodes)
{
    __shared__ SmemU sm;

    if (blockIdx.x < GH_BLOCKS) {
        int bx = blockIdx.x % GH_BX;
        int by = blockIdx.x / GH_BX;
        gemm_body<0>(sm.g, gf, whh, bhh, g_gh, nullptr, 3 * F, F, bx, by);
        return;
    }

    const int g    = blockIdx.x - GH_BLOCKS;
    const int tid  = threadIdx.x;
    const int warp = tid >> 5;
    const int lane = tid & 31;

    // c_g = relu(g_feats[g]) . lw[0:256] + b
    {
        float v = fmaxf(gf[g * F + tid], 0.f) * lw[tid];
        #pragma unroll
        for (int o = 16; o; o >>= 1) v += __shfl_xor_sync(0xffffffffu, v, o);
        if (lane == 0) sm.p.red[warp] = v;
    }
    if (tid == 0)  sm.p.bnd[0] = lbound(seg, n_nodes, g);
    if (tid == 32) sm.p.bnd[1] = lbound(seg, n_nodes, g + 1);
    __syncthreads();
    if (tid == 0) {
        float c = lb[0];
        #pragma unroll
        for (int w = 0; w < 8; ++w) c += sm.p.red[w];
        sm.p.c = c;
    }
    __syncthreads();
    const float c     = sm.p.c;
    const int   start = sm.p.bnd[0];
    const int   end   = sm.p.bnd[1];

    // per-lane chunks of logit_w node half (coalesced mapping)
    float lwA[4], lwB[4];
    {
        float4 a = __ldg(reinterpret_cast<const float4*>(lw + F) + lane);
        float4 b = __ldg(reinterpret_cast<const float4*>(lw + F + 128) + lane);
        lwA[0]=a.x; lwA[1]=a.y; lwA[2]=a.z; lwA[3]=a.w;
        lwB[0]=b.x; lwB[1]=b.y; lwB[2]=b.z; lwB[3]=b.w;
    }

    float s = 0.f;
    float acc[8] = {0.f, 0.f, 0.f, 0.f, 0.f, 0.f, 0.f, 0.f};

    int n = start + warp;
    // ---- main loop: 3 nodes per iteration, 6 front-batched contiguous LDG.128 ----
    for (; n + 16 < end; n += 24) {
        const float4* p = reinterpret_cast<const float4*>(nf + (size_t)n * F) + lane;
        float4 a0 = ldcs4(p),        a1 = ldcs4(p + 32);
        float4 b0 = ldcs4(p + 512),  b1 = ldcs4(p + 544);
        float4 c0 = ldcs4(p + 1024), c1 = ldcs4(p + 1056);

        float q1 = a0.x * lwA[0], q2 = b0.x * lwA[0], q3 = c0.x * lwA[0];
        q1 = fmaf(a0.y, lwA[1], q1); q2 = fmaf(b0.y, lwA[1], q2); q3 = fmaf(c0.y, lwA[1], q3);
        q1 = fmaf(a0.z, lwA[2], q1); q2 = fmaf(b0.z, lwA[2], q2); q3 = fmaf(c0.z, lwA[2], q3);
        q1 = fmaf(a0.w, lwA[3], q1); q2 = fmaf(b0.w, lwA[3], q2); q3 = fmaf(c0.w, lwA[3], q3);
        q1 = fmaf(a1.x, lwB[0], q1); q2 = fmaf(b1.x, lwB[0], q2); q3 = fmaf(c1.x, lwB[0], q3);
        q1 = fmaf(a1.y, lwB[1], q1); q2 = fmaf(b1.y, lwB[1], q2); q3 = fmaf(c1.y, lwB[1], q3);
        q1 = fmaf(a1.z, lwB[2], q1); q2 = fmaf(b1.z, lwB[2], q2); q3 = fmaf(c1.z, lwB[2], q3);
        q1 = fmaf(a1.w, lwB[3], q1); q2 = fmaf(b1.w, lwB[3], q2); q3 = fmaf(c1.w, lwB[3], q3);
        #pragma unroll
        for (int o = 16; o; o >>= 1) {
            q1 += __shfl_xor_sync(0xffffffffu, q1, o);
            q2 += __shfl_xor_sync(0xffffffffu, q2, o);
            q3 += __shfl_xor_sync(0xffffffffu, q3, o);
        }
        float t1 = c + q1, t2 = c + q2, t3 = c + q3;
        float z1 = t1 > 0.f ? t1 : 0.01f * t1;
        float z2 = t2 > 0.f ? t2 : 0.01f * t2;
        float z3 = t3 > 0.f ? t3 : 0.01f * t3;
        float e1 = __expf(z1), e2 = __expf(z2), e3 = __expf(z3);
        s += (e1 + e2) + e3;
        acc[0] = fmaf(e1, a0.x, fmaf(e2, b0.x, fmaf(e3, c0.x, acc[0])));
        acc[1] = fmaf(e1, a0.y, fmaf(e2, b0.y, fmaf(e3, c0.y, acc[1])));
        acc[2] = fmaf(e1, a0.z, fmaf(e2, b0.z, fmaf(e3, c0.z, acc[2])));
        acc[3] = fmaf(e1, a0.w, fmaf(e2, b0.w, fmaf(e3, c0.w, acc[3])));
        acc[4] = fmaf(e1, a1.x, fmaf(e2, b1.x, fmaf(e3, c1.x, acc[4])));
        acc[5] = fmaf(e1, a1.y, fmaf(e2, b1.y, fmaf(e3, c1.y, acc[5])));
        acc[6] = fmaf(e1, a1.z, fmaf(e2, b1.z, fmaf(e3, c1.z, acc[6])));
        acc[7] = fmaf(e1, a1.w, fmaf(e2, b1.w, fmaf(e3, c1.w, acc[7])));
    }
    // ---- tail: up to 2 nodes per warp ----
    for (; n < end; n += 8) {
        const float4* p = reinterpret_cast<const float4*>(nf + (size_t)n * F) + lane;
        float4 f0 = ldcs4(p), f1 = ldcs4(p + 32);
        float d = f0.x * lwA[0];
        d = fmaf(f0.y, lwA[1], d); d = fmaf(f0.z, lwA[2], d); d = fmaf(f0.w, lwA[3], d);
        d = fmaf(f1.x, lwB[0], d); d = fmaf(f1.y, lwB[1], d);
        d = fmaf(f1.z, lwB[2], d); d = fmaf(f1.w, lwB[3], d);
        #pragma unroll
        for (int o = 16; o; o >>= 1) d += __shfl_xor_sync(0xffffffffu, d, o);
        float t  = c + d;
        float z  = t > 0.f ? t : 0.01f * t;
        float e  = __expf(z);
        s += e;
        acc[0] = fmaf(e, f0.x, acc[0]);
        acc[1] = fmaf(e, f0.y, acc[1]);
        acc[2] = fmaf(e, f0.z, acc[2]);
        acc[3] = fmaf(e, f0.w, acc[3]);
        acc[4] = fmaf(e, f1.x, acc[4]);
        acc[5] = fmaf(e, f1.y, acc[5]);
        acc[6] = fmaf(e, f1.z, acc[6]);
        acc[7] = fmaf(e, f1.w, acc[7]);
    }

    if (lane == 0) sm.p.s[warp] = s;
    #pragma unroll
    for (int j = 0; j < 4; ++j) {
        sm.p.acc[warp][lane * 4 + j]       = acc[j];
        sm.p.acc[warp][128 + lane * 4 + j] = acc[4 + j];
    }
    __syncthreads();

    float S = 0.f, val = 0.f;
    #pragma unroll
    for (int w = 0; w < 8; ++w) {
        S   += sm.p.s[w];
        val += sm.p.acc[w][tid];
    }
    g_wf[g * F + tid] = (S > 0.f) ? val / S : 0.f;
    if (tid == 0) g_cnt[g] = end - start;
}

// proj: x = elu(wf @ proj_w.T + proj_b), zeroed for empty graphs
__global__ void __launch_bounds__(256) proj_kernel(
    const float* __restrict__ pw, const float* __restrict__ pb)
{
    __shared__ SmemGemm sg;
    gemm_body<1>(sg, g_wf, pw, pb, g_x, g_cnt, F, F, blockIdx.x, blockIdx.y);
}

// ---------------- GI = x @ w_ih.T + b_ih : BM=32, BN=64 -> 384 blocks ----------
__global__ void __launch_bounds__(256) gi_kernel(
    const float* __restrict__ wih, const float* __restrict__ bih)
{
    __shared__ float As[2][16][36];
    __shared__ float Ws[2][16][68];

    const int tid  = threadIdx.x;
    const int tx   = tid & 15;       // 4 cols each -> 64
    const int ty   = tid >> 4;       // 2 rows each -> 32
    const int row0 = blockIdx.x * 32;
    const int col0 = blockIdx.y * 64;

    const int arow = tid >> 2;       // A: tid<128 -> rows 0..31
    const int ac4  = tid & 3;
    const int wrow = tid >> 2;       // W: all threads -> rows 0..63
    const int wc4  = tid & 3;

    float4 aR, wR;
    auto ldg = [&](int k0) {
        if (tid < 128)
            aR = *reinterpret_cast<const float4*>(g_x + (size_t)(row0 + arow) * F + k0 + ac4 * 4);
        wR = *reinterpret_cast<const float4*>(wih + (size_t)(col0 + wrow) * F + k0 + wc4 * 4);
    };
    auto sts = [&](int buf) {
        if (tid < 128) {
            As[buf][ac4 * 4 + 0][arow] = aR.x;
            As[buf][ac4 * 4 + 1][arow] = aR.y;
            As[buf][ac4 * 4 + 2][arow] = aR.z;
            As[buf][ac4 * 4 + 3][arow] = aR.w;
        }
        Ws[buf][wc4 * 4 + 0][wrow] = wR.x;
        Ws[buf][wc4 * 4 + 1][wrow] = wR.y;
        Ws[buf][wc4 * 4 + 2][wrow] = wR.z;
        Ws[buf][wc4 * 4 + 3][wrow] = wR.w;
    };

    uint64_t acc2[2][2] = {{0ull, 0ull}, {0ull, 0ull}};

    ldg(0); sts(0); __syncthreads();
    for (int t = 0; t < 16; ++t) {
        if (t + 1 < 16) ldg((t + 1) * 16);
        const int buf = t & 1;
        #pragma unroll
        for (int kk = 0; kk < 16; ++kk) {
            float2 ra = *reinterpret_cast<const float2*>(&As[buf][kk][ty * 2]);
            float4 rw = *reinterpret_cast<const float4*>(&Ws[buf][kk][tx * 4]);
            uint64_t b01 = pack2(rw.x, rw.y);
            uint64_t b23 = pack2(rw.z, rw.w);
            uint64_t a0 = bcast2(ra.x), a1 = bcast2(ra.y);
            ffma2(acc2[0][0], a0, b01); ffma2(acc2[0][1], a0, b23);
            ffma2(acc2[1][0], a1, b01); ffma2(acc2[1][1], a1, b23);
        }
        if (t + 1 < 16) { sts((t + 1) & 1); __syncthreads(); }
    }

    #pragma unroll
    for (int i = 0; i < 2; ++i) {
        int r = row0 + ty * 2 + i;
        #pragma unroll
        for (int j = 0; j < 2; ++j) {
            int col = col0 + tx * 4 + j * 2;
            float2 v = unpack2(acc2[i][j]);
            v.x += bih[col];
            v.y += bih[col + 1];
            *reinterpret_cast<float2*>(g_gi + (size_t)r * (3 * F) + col) = v;
        }
    }
}

// ---------------- GRU elementwise (float2, 512 blocks) ----------------
__global__ void __launch_bounds__(256) gru_kernel(
    const float* __restrict__ gf, float* __restrict__ out)
{
    int idx2 = blockIdx.x * blockDim.x + threadIdx.x;
    if (idx2 >= NG * F / 2) return;
    int g  = idx2 / (F / 2);
    int d2 = (idx2 % (F / 2)) * 2;
    const float* gi = g_gi + (size_t)g * 3 * F;
    const float* gh = g_gh + (size_t)g * 3 * F;

    float2 ir  = *reinterpret_cast<const float2*>(gi + d2);
    float2 iz  = *reinterpret_cast<const float2*>(gi + F + d2);
    float2 inn = *reinterpret_cast<const float2*>(gi + 2 * F + d2);
    float2 hr  = *reinterpret_cast<const float2*>(gh + d2);
    float2 hz  = *reinterpret_cast<const float2*>(gh + F + d2);
    float2 hn  = *reinterpret_cast<const float2*>(gh + 2 * F + d2);
    float2 h   = *reinterpret_cast<const float2*>(gf + (size_t)g * F + d2);

    float2 o;
    {
        float r = 0.5f * fast_tanh(0.5f * (ir.x + hr.x)) + 0.5f;
        float z = 0.5f * fast_tanh(0.5f * (iz.x + hz.x)) + 0.5f;
        float nn = fast_tanh(fmaf(r, hn.x, inn.x));
        o.x = fmaf(1.f - z, nn, z * h.x);
    }
    {
        float r = 0.5f * fast_tanh(0.5f * (ir.y + hr.y)) + 0.5f;
        float z = 0.5f * fast_tanh(0.5f * (iz.y + hz.y)) + 0.5f;
        float nn = fast_tanh(fmaf(r, hn.y, inn.y));
        o.y = fmaf(1.f - z, nn, z * h.y);
    }
    *reinterpret_cast<float2*>(out + (size_t)g * F + d2) = o;
}

// ---------------- launch ----------------
extern "C" void kernel_launch(void* const* d_in, const int* in_sizes, int n_in,
                              void* d_out, int out_size)
{
    int o = (n_in >= 12) ? 1 : 0;
    const float* nf  = (const float*)d_in[0];
    const float* gf  = (const float*)d_in[1];
    const int*   seg = (const int*)  d_in[2];
    const float* lw  = (const float*)d_in[3 + o];
    const float* lb  = (const float*)d_in[4 + o];
    const float* pw  = (const float*)d_in[5 + o];
    const float* pb  = (const float*)d_in[6 + o];
    const float* wih = (const float*)d_in[7 + o];
    const float* whh = (const float*)d_in[8 + o];
    const float* bih = (const float*)d_in[9 + o];
    const float* bhh = (const float*)d_in[10 + o];
    float* out = (float*)d_out;
    int n_nodes = in_sizes[0] / F;

    fused_pool_gh_kernel<<<GH_BLOCKS + NG, 256>>>(nf, gf, lw, lb, whh, bhh, seg, n_nodes);
    proj_kernel<<<dim3(NG / BM, F / BN), 256>>>(pw, pb);
    gi_kernel<<<dim3(NG / 32, (3 * F) / 64), 256>>>(wih, bih);
    gru_kernel<<<(NG * F / 2 + 255) / 256, 256>>>(gf, out);
}

// round 12
// speedup vs baseline: 1.0024x; 1.0024x over previous
#include <cuda_runtime.h>
#include <math.h>
#include <stdint.h>

#define F   256
#define NG  1024

// GEMM tile config (GH/proj): BM=BN=64, BK=16, TM=TN=4, 256 threads
#define BM 64
#define BN 64
#define BK 16

#define GH_BX 16                  // 1024/64
#define GH_BY 12                  // 768/64
#define GH_BLOCKS (GH_BX * GH_BY) // 192

// ---------------- scratch ----------------
__device__ float g_wf[NG * F];
__device__ int   g_cnt[NG];
__device__ float g_x[NG * F];
__device__ float g_gi[NG * 3 * F];
__device__ float g_gh[NG * 3 * F];

// ---------------- f32x2 packed-math helpers ----------------
__device__ __forceinline__ uint64_t pack2(float x, float y) {
    uint64_t r; asm("mov.b64 %0, {%1, %2};" : "=l"(r) : "f"(x), "f"(y)); return r;
}
__device__ __forceinline__ uint64_t bcast2(float x) {
    uint64_t r; asm("mov.b64 %0, {%1, %1};" : "=l"(r) : "f"(x)); return r;
}
__device__ __forceinline__ void ffma2(uint64_t& d, uint64_t a, uint64_t b) {
    asm("fma.rn.f32x2 %0, %1, %2, %0;" : "+l"(d) : "l"(a), "l"(b));
}
__device__ __forceinline__ float2 unpack2(uint64_t v) {
    float2 f; asm("mov.b64 {%0, %1}, %2;" : "=f"(f.x), "=f"(f.y) : "l"(v)); return f;
}
__device__ __forceinline__ float fast_tanh(float x) {
    float r; asm("tanh.approx.f32 %0, %1;" : "=f"(r) : "f"(x)); return r;
}
__device__ __forceinline__ float4 ldcs4(const float4* p) {
    float4 v;
    asm("ld.global.cs.v4.f32 {%0,%1,%2,%3}, [%4];"
        : "=f"(v.x), "=f"(v.y), "=f"(v.z), "=f"(v.w) : "l"(p));
    return v;
}

// ---------------- shared memory layouts ----------------
struct SmemGemm {
    float As[2][BK][BM + 4];
    float Ws[2][BK][BN + 4];
};
struct SmemPool {
    float red[8];
    float c;
    float s[8];
    int   bnd[2];
    float acc[8][F];
};
union SmemU { SmemGemm g; SmemPool p; };

// ---------------- GEMM body: C[M,N] = A[M,K] @ W[N,K]^T + bias ----------------
template <int EPI>
__device__ __forceinline__ void gemm_body(
    SmemGemm& S,
    const float* __restrict__ A, const float* __restrict__ W,
    const float* __restrict__ bias, float* __restrict__ C,
    const int* __restrict__ cnt, int N, int K, int bx, int by)
{
    const int tid  = threadIdx.x;
    const int tx   = tid % (BN / 4);
    const int ty   = tid / (BN / 4);
    const int row0 = bx * BM;
    const int col0 = by * BN;

    float4 aR, wR;
    const int r_ld  = tid / (BK / 4);
    const int c4_ld = tid % (BK / 4);

    auto ldg = [&](int k0) {
        aR = *reinterpret_cast<const float4*>(A + (size_t)(row0 + r_ld) * K + k0 + c4_ld * 4);
        wR = *reinterpret_cast<const float4*>(W + (size_t)(col0 + r_ld) * K + k0 + c4_ld * 4);
    };
    auto sts = [&](int buf) {
        S.As[buf][c4_ld * 4 + 0][r_ld] = aR.x;
        S.As[buf][c4_ld * 4 + 1][r_ld] = aR.y;
        S.As[buf][c4_ld * 4 + 2][r_ld] = aR.z;
        S.As[buf][c4_ld * 4 + 3][r_ld] = aR.w;
        S.Ws[buf][c4_ld * 4 + 0][r_ld] = wR.x;
        S.Ws[buf][c4_ld * 4 + 1][r_ld] = wR.y;
        S.Ws[buf][c4_ld * 4 + 2][r_ld] = wR.z;
        S.Ws[buf][c4_ld * 4 + 3][r_ld] = wR.w;
    };

    uint64_t acc2[4][2];
    #pragma unroll
    for (int i = 0; i < 4; ++i) { acc2[i][0] = 0ull; acc2[i][1] = 0ull; }

    const int T = K / BK;
    ldg(0);
    sts(0);
    __syncthreads();

    for (int t = 0; t < T; ++t) {
        if (t + 1 < T) ldg((t + 1) * BK);
        const int buf = t & 1;
        #pragma unroll
        for (int kk = 0; kk < BK; ++kk) {
            float4 ra = *reinterpret_cast<const float4*>(&S.As[buf][kk][ty * 4]);
            float4 rw = *reinterpret_cast<const float4*>(&S.Ws[buf][kk][tx * 4]);
            uint64_t b01 = pack2(rw.x, rw.y);
            uint64_t b23 = pack2(rw.z, rw.w);
            uint64_t a0 = bcast2(ra.x), a1 = bcast2(ra.y);
            uint64_t a2 = bcast2(ra.z), a3 = bcast2(ra.w);
            ffma2(acc2[0][0], a0, b01); ffma2(acc2[0][1], a0, b23);
            ffma2(acc2[1][0], a1, b01); ffma2(acc2[1][1], a1, b23);
            ffma2(acc2[2][0], a2, b01); ffma2(acc2[2][1], a2, b23);
            ffma2(acc2[3][0], a3, b01); ffma2(acc2[3][1], a3, b23);
        }
        if (t + 1 < T) {
            sts((t + 1) & 1);
            __syncthreads();
        }
    }

    #pragma unroll
    for (int i = 0; i < 4; ++i) {
        int r = row0 + ty * 4 + i;
        int cz = (EPI == 1) ? cnt[r] : 1;
        #pragma unroll
        for (int j = 0; j < 2; ++j) {
            int col = col0 + tx * 4 + j * 2;
            float2 v = unpack2(acc2[i][j]);
            v.x += bias[col];
            v.y += bias[col + 1];
            if (EPI == 1) {
                v.x = v.x > 0.f ? v.x : expm1f(v.x);
                v.y = v.y > 0.f ? v.y : expm1f(v.y);
                if (cz == 0) { v.x = 0.f; v.y = 0.f; }
            }
            *reinterpret_cast<float2*>(C + (size_t)r * N + col) = v;
        }
    }
}

// ---------------- binary search (segment_ids sorted) ----------------
__device__ __forceinline__ int lbound(const int* __restrict__ seg, int n, int key) {
    int lo = 0, hi = n;
    while (lo < hi) {
        int mid = (lo + hi) >> 1;
        if (__ldg(seg + mid) < key) lo = mid + 1; else hi = mid;
    }
    return lo;
}

// ---------------- fused: GH GEMM blocks + pool blocks ----------------
// Pool: unnormalized exp accumulation, coalesced lanes, unroll-4 with 8
// front-batched contiguous LDG.128, launch_bounds(256,3). This exact config
// measured 59.3us @ DRAM 58.8% — do not perturb (unroll-3@4blk regressed).
__global__ void __launch_bounds__(256, 3) fused_pool_gh_kernel(
    const float* __restrict__ nf, const float* __restrict__ gf,
    const float* __restrict__ lw, const float* __restrict__ lb,
    const float* __restrict__ whh, const float* __restrict__ bhh,
    const int* __restrict__ seg, int n_nodes)
{
    __shared__ SmemU sm;

    if (blockIdx.x < GH_BLOCKS) {
        int bx = blockIdx.x % GH_BX;
        int by = blockIdx.x / GH_BX;
        gemm_body<0>(sm.g, gf, whh, bhh, g_gh, nullptr, 3 * F, F, bx, by);
        return;
    }

    const int g    = blockIdx.x - GH_BLOCKS;
    const int tid  = threadIdx.x;
    const int warp = tid >> 5;
    const int lane = tid & 31;

    // c_g = relu(g_feats[g]) . lw[0:256] + b
    {
        float v = fmaxf(gf[g * F + tid], 0.f) * lw[tid];
        #pragma unroll
        for (int o = 16; o; o >>= 1) v += __shfl_xor_sync(0xffffffffu, v, o);
        if (lane == 0) sm.p.red[warp] = v;
    }
    if (tid == 0)  sm.p.bnd[0] = lbound(seg, n_nodes, g);
    if (tid == 32) sm.p.bnd[1] = lbound(seg, n_nodes, g + 1);
    __syncthreads();
    if (tid == 0) {
        float c = lb[0];
        #pragma unroll
        for (int w = 0; w < 8; ++w) c += sm.p.red[w];
        sm.p.c = c;
    }
    __syncthreads();
    const float c     = sm.p.c;
    const int   start = sm.p.bnd[0];
    const int   end   = sm.p.bnd[1];

    // per-lane chunks of logit_w node half (coalesced mapping)
    float lwA[4], lwB[4];
    {
        float4 a = __ldg(reinterpret_cast<const float4*>(lw + F) + lane);
        float4 b = __ldg(reinterpret_cast<const float4*>(lw + F + 128) + lane);
        lwA[0]=a.x; lwA[1]=a.y; lwA[2]=a.z; lwA[3]=a.w;
        lwB[0]=b.x; lwB[1]=b.y; lwB[2]=b.z; lwB[3]=b.w;
    }

    float s = 0.f;
    float acc[8] = {0.f, 0.f, 0.f, 0.f, 0.f, 0.f, 0.f, 0.f};

    int n = start + warp;
    // ---- main loop: 4 nodes per iteration, 8 front-batched contiguous LDG.128 ----
    for (; n + 24 < end; n += 32) {
        const float4* p = reinterpret_cast<const float4*>(nf + (size_t)n * F) + lane;
        float4 a0 = ldcs4(p),        a1 = ldcs4(p + 32);
        float4 b0 = ldcs4(p + 512),  b1 = ldcs4(p + 544);
        float4 c0 = ldcs4(p + 1024), c1 = ldcs4(p + 1056);
        float4 d0 = ldcs4(p + 1536), d1 = ldcs4(p + 1568);

        float q1 = a0.x * lwA[0], q2 = b0.x * lwA[0];
        float q3 = c0.x * lwA[0], q4 = d0.x * lwA[0];
        q1 = fmaf(a0.y, lwA[1], q1); q2 = fmaf(b0.y, lwA[1], q2);
        q3 = fmaf(c0.y, lwA[1], q3); q4 = fmaf(d0.y, lwA[1], q4);
        q1 = fmaf(a0.z, lwA[2], q1); q2 = fmaf(b0.z, lwA[2], q2);
        q3 = fmaf(c0.z, lwA[2], q3); q4 = fmaf(d0.z, lwA[2], q4);
        q1 = fmaf(a0.w, lwA[3], q1); q2 = fmaf(b0.w, lwA[3], q2);
        q3 = fmaf(c0.w, lwA[3], q3); q4 = fmaf(d0.w, lwA[3], q4);
        q1 = fmaf(a1.x, lwB[0], q1); q2 = fmaf(b1.x, lwB[0], q2);
        q3 = fmaf(c1.x, lwB[0], q3); q4 = fmaf(d1.x, lwB[0], q4);
        q1 = fmaf(a1.y, lwB[1], q1); q2 = fmaf(b1.y, lwB[1], q2);
        q3 = fmaf(c1.y, lwB[1], q3); q4 = fmaf(d1.y, lwB[1], q4);
        q1 = fmaf(a1.z, lwB[2], q1); q2 = fmaf(b1.z, lwB[2], q2);
        q3 = fmaf(c1.z, lwB[2], q3); q4 = fmaf(d1.z, lwB[2], q4);
        q1 = fmaf(a1.w, lwB[3], q1); q2 = fmaf(b1.w, lwB[3], q2);
        q3 = fmaf(c1.w, lwB[3], q3); q4 = fmaf(d1.w, lwB[3], q4);
        #pragma unroll
        for (int o = 16; o; o >>= 1) {
            q1 += __shfl_xor_sync(0xffffffffu, q1, o);
            q2 += __shfl_xor_sync(0xffffffffu, q2, o);
            q3 += __shfl_xor_sync(0xffffffffu, q3, o);
            q4 += __shfl_xor_sync(0xffffffffu, q4, o);
        }
        float t1 = c + q1, t2 = c + q2, t3 = c + q3, t4 = c + q4;
        float z1 = t1 > 0.f ? t1 : 0.01f * t1;
        float z2 = t2 > 0.f ? t2 : 0.01f * t2;
        float z3 = t3 > 0.f ? t3 : 0.01f * t3;
        float z4 = t4 > 0.f ? t4 : 0.01f * t4;
        float e1 = __expf(z1), e2 = __expf(z2);
        float e3 = __expf(z3), e4 = __expf(z4);
        s += (e1 + e2) + (e3 + e4);
        acc[0] = fmaf(e1, a0.x, fmaf(e2, b0.x, fmaf(e3, c0.x, fmaf(e4, d0.x, acc[0]))));
        acc[1] = fmaf(e1, a0.y, fmaf(e2, b0.y, fmaf(e3, c0.y, fmaf(e4, d0.y, acc[1]))));
        acc[2] = fmaf(e1, a0.z, fmaf(e2, b0.z, fmaf(e3, c0.z, fmaf(e4, d0.z, acc[2]))));
        acc[3] = fmaf(e1, a0.w, fmaf(e2, b0.w, fmaf(e3, c0.w, fmaf(e4, d0.w, acc[3]))));
        acc[4] = fmaf(e1, a1.x, fmaf(e2, b1.x, fmaf(e3, c1.x, fmaf(e4, d1.x, acc[4]))));
        acc[5] = fmaf(e1, a1.y, fmaf(e2, b1.y, fmaf(e3, c1.y, fmaf(e4, d1.y, acc[5]))));
        acc[6] = fmaf(e1, a1.z, fmaf(e2, b1.z, fmaf(e3, c1.z, fmaf(e4, d1.z, acc[6]))));
        acc[7] = fmaf(e1, a1.w, fmaf(e2, b1.w, fmaf(e3, c1.w, fmaf(e4, d1.w, acc[7]))));
    }
    // ---- tail: up to 3 nodes per warp ----
    for (; n < end; n += 8) {
        const float4* p = reinterpret_cast<const float4*>(nf + (size_t)n * F) + lane;
        float4 f0 = ldcs4(p), f1 = ldcs4(p + 32);
        float d = f0.x * lwA[0];
        d = fmaf(f0.y, lwA[1], d); d = fmaf(f0.z, lwA[2], d); d = fmaf(f0.w, lwA[3], d);
        d = fmaf(f1.x, lwB[0], d); d = fmaf(f1.y, lwB[1], d);
        d = fmaf(f1.z, lwB[2], d); d = fmaf(f1.w, lwB[3], d);
        #pragma unroll
        for (int o = 16; o; o >>= 1) d += __shfl_xor_sync(0xffffffffu, d, o);
        float t  = c + d;
        float z  = t > 0.f ? t : 0.01f * t;
        float e  = __expf(z);
        s += e;
        acc[0] = fmaf(e, f0.x, acc[0]);
        acc[1] = fmaf(e, f0.y, acc[1]);
        acc[2] = fmaf(e, f0.z, acc[2]);
        acc[3] = fmaf(e, f0.w, acc[3]);
        acc[4] = fmaf(e, f1.x, acc[4]);
        acc[5] = fmaf(e, f1.y, acc[5]);
        acc[6] = fmaf(e, f1.z, acc[6]);
        acc[7] = fmaf(e, f1.w, acc[7]);
    }

    if (lane == 0) sm.p.s[warp] = s;
    #pragma unroll
    for (int j = 0; j < 4; ++j) {
        sm.p.acc[warp][lane * 4 + j]       = acc[j];
        sm.p.acc[warp][128 + lane * 4 + j] = acc[4 + j];
    }
    __syncthreads();

    float S = 0.f, val = 0.f;
    #pragma unroll
    for (int w = 0; w < 8; ++w) {
        S   += sm.p.s[w];
        val += sm.p.acc[w][tid];
    }
    g_wf[g * F + tid] = (S > 0.f) ? val / S : 0.f;
    if (tid == 0) g_cnt[g] = end - start;
}

// proj: x = elu(wf @ proj_w.T + proj_b), zeroed for empty graphs
__global__ void __launch_bounds__(256) proj_kernel(
    const float* __restrict__ pw, const float* __restrict__ pb)
{
    __shared__ SmemGemm sg;
    gemm_body<1>(sg, g_wf, pw, pb, g_x, g_cnt, F, F, blockIdx.x, blockIdx.y);
}

// ---------------- GI = x @ w_ih.T + b_ih : BM=32, BN=64 -> 384 blocks ----------
__global__ void __launch_bounds__(256) gi_kernel(
    const float* __restrict__ wih, const float* __restrict__ bih)
{
    __shared__ float As[2][16][36];
    __shared__ float Ws[2][16][68];

    const int tid  = threadIdx.x;
    const int tx   = tid & 15;       // 4 cols each -> 64
    const int ty   = tid >> 4;       // 2 rows each -> 32
    const int row0 = blockIdx.x * 32;
    const int col0 = blockIdx.y * 64;

    const int arow = tid >> 2;       // A: tid<128 -> rows 0..31
    const int ac4  = tid & 3;
    const int wrow = tid >> 2;       // W: all threads -> rows 0..63
    const int wc4  = tid & 3;

    float4 aR, wR;
    auto ldg = [&](int k0) {
        if (tid < 128)
            aR = *reinterpret_cast<const float4*>(g_x + (size_t)(row0 + arow) * F + k0 + ac4 * 4);
        wR = *reinterpret_cast<const float4*>(wih + (size_t)(col0 + wrow) * F + k0 + wc4 * 4);
    };
    auto sts = [&](int buf) {
        if (tid < 128) {
            As[buf][ac4 * 4 + 0][arow] = aR.x;
            As[buf][ac4 * 4 + 1][arow] = aR.y;
            As[buf][ac4 * 4 + 2][arow] = aR.z;
            As[buf][ac4 * 4 + 3][arow] = aR.w;
        }
        Ws[buf][wc4 * 4 + 0][wrow] = wR.x;
        Ws[buf][wc4 * 4 + 1][wrow] = wR.y;
        Ws[buf][wc4 * 4 + 2][wrow] = wR.z;
        Ws[buf][wc4 * 4 + 3][wrow] = wR.w;
    };

    uint64_t acc2[2][2] = {{0ull, 0ull}, {0ull, 0ull}};

    ldg(0); sts(0); __syncthreads();
    for (int t = 0; t < 16; ++t) {
        if (t + 1 < 16) ldg((t + 1) * 16);
        const int buf = t & 1;
        #pragma unroll
        for (int kk = 0; kk < 16; ++kk) {
            float2 ra = *reinterpret_cast<const float2*>(&As[buf][kk][ty * 2]);
            float4 rw = *reinterpret_cast<const float4*>(&Ws[buf][kk][tx * 4]);
            uint64_t b01 = pack2(rw.x, rw.y);
            uint64_t b23 = pack2(rw.z, rw.w);
            uint64_t a0 = bcast2(ra.x), a1 = bcast2(ra.y);
            ffma2(acc2[0][0], a0, b01); ffma2(acc2[0][1], a0, b23);
            ffma2(acc2[1][0], a1, b01); ffma2(acc2[1][1], a1, b23);
        }
        if (t + 1 < 16) { sts((t + 1) & 1); __syncthreads(); }
    }

    #pragma unroll
    for (int i = 0; i < 2; ++i) {
        int r = row0 + ty * 2 + i;
        #pragma unroll
        for (int j = 0; j < 2; ++j) {
            int col = col0 + tx * 4 + j * 2;
            float2 v = unpack2(acc2[i][j]);
            v.x += bih[col];
            v.y += bih[col + 1];
            *reinterpret_cast<float2*>(g_gi + (size_t)r * (3 * F) + col) = v;
        }
    }
}

// ---------------- GRU elementwise (float2, 512 blocks) ----------------
__global__ void __launch_bounds__(256) gru_kernel(
    const float* __restrict__ gf, float* __restrict__ out)
{
    int idx2 = blockIdx.x * blockDim.x + threadIdx.x;
    if (idx2 >= NG * F / 2) return;
    int g  = idx2 / (F / 2);
    int d2 = (idx2 % (F / 2)) * 2;
    const float* gi = g_gi + (size_t)g * 3 * F;
    const float* gh = g_gh + (size_t)g * 3 * F;

    float2 ir  = *reinterpret_cast<const float2*>(gi + d2);
    float2 iz  = *reinterpret_cast<const float2*>(gi + F + d2);
    float2 inn = *reinterpret_cast<const float2*>(gi + 2 * F + d2);
    float2 hr  = *reinterpret_cast<const float2*>(gh + d2);
    float2 hz  = *reinterpret_cast<const float2*>(gh + F + d2);
    float2 hn  = *reinterpret_cast<const float2*>(gh + 2 * F + d2);
    float2 h   = *reinterpret_cast<const float2*>(gf + (size_t)g * F + d2);

    float2 o;
    {
        float r = 0.5f * fast_tanh(0.5f * (ir.x + hr.x)) + 0.5f;
        float z = 0.5f * fast_tanh(0.5f * (iz.x + hz.x)) + 0.5f;
        float nn = fast_tanh(fmaf(r, hn.x, inn.x));
        o.x = fmaf(1.f - z, nn, z * h.x);
    }
    {
        float r = 0.5f * fast_tanh(0.5f * (ir.y + hr.y)) + 0.5f;
        float z = 0.5f * fast_tanh(0.5f * (iz.y + hz.y)) + 0.5f;
        float nn = fast_tanh(fmaf(r, hn.y, inn.y));
        o.y = fmaf(1.f - z, nn, z * h.y);
    }
    *reinterpret_cast<float2*>(out + (size_t)g * F + d2) = o;
}

// ---------------- launch ----------------
extern "C" void kernel_launch(void* const* d_in, const int* in_sizes, int n_in,
                              void* d_out, int out_size)
{
    int o = (n_in >= 12) ? 1 : 0;
    const float* nf  = (const float*)d_in[0];
    const float* gf  = (const float*)d_in[1];
    const int*   seg = (const int*)  d_in[2];
    const float* lw  = (const float*)d_in[3 + o];
    const float* lb  = (const float*)d_in[4 + o];
    const float* pw  = (const float*)d_in[5 + o];
    const float* pb  = (const float*)d_in[6 + o];
    const float* wih = (const float*)d_in[7 + o];
    const float* whh = (const float*)d_in[8 + o];
    const float* bih = (const float*)d_in[9 + o];
    const float* bhh = (const float*)d_in[10 + o];
    float* out = (float*)d_out;
    int n_nodes = in_sizes[0] / F;

    fused_pool_gh_kernel<<<GH_BLOCKS + NG, 256>>>(nf, gf, lw, lb, whh, bhh, seg, n_nodes);
    proj_kernel<<<dim3(NG / BM, F / BN), 256>>>(pw, pb);
    gi_kernel<<<dim3(NG / 32, (3 * F) / 64), 256>>>(wih, bih);
    gru_kernel<<<(NG * F / 2 + 255) / 256, 256>>>(gf, out);
}

// round 13
// speedup vs baseline: 1.0193x; 1.0169x over previous
#include <cuda_runtime.h>
#include <math.h>
#include <stdint.h>

#define F   256
#define NG  1024

// GEMM tile config: BM=BN=64, BK=16, TM=TN=4, 256 threads
#define BM 64
#define BN 64
#define BK 16

#define GH_BX 16                  // 1024/64
#define GH_BY 12                  // 768/64
#define GH_BLOCKS (GH_BX * GH_BY) // 192

// ---------------- scratch ----------------
__device__ float g_wf[NG * F];
__device__ int   g_cnt[NG];
__device__ float g_x[NG * F];
__device__ float g_gi[NG * 3 * F];
__device__ float g_gh[NG * 3 * F];

// ---------------- f32x2 packed-math helpers ----------------
__device__ __forceinline__ uint64_t pack2(float x, float y) {
    uint64_t r; asm("mov.b64 %0, {%1, %2};" : "=l"(r) : "f"(x), "f"(y)); return r;
}
__device__ __forceinline__ uint64_t bcast2(float x) {
    uint64_t r; asm("mov.b64 %0, {%1, %1};" : "=l"(r) : "f"(x)); return r;
}
__device__ __forceinline__ void ffma2(uint64_t& d, uint64_t a, uint64_t b) {
    asm("fma.rn.f32x2 %0, %1, %2, %0;" : "+l"(d) : "l"(a), "l"(b));
}
__device__ __forceinline__ float2 unpack2(uint64_t v) {
    float2 f; asm("mov.b64 {%0, %1}, %2;" : "=f"(f.x), "=f"(f.y) : "l"(v)); return f;
}
__device__ __forceinline__ float fast_tanh(float x) {
    float r; asm("tanh.approx.f32 %0, %1;" : "=f"(r) : "f"(x)); return r;
}
__device__ __forceinline__ float4 ldcs4(const float4* p) {
    float4 v;
    asm("ld.global.cs.v4.f32 {%0,%1,%2,%3}, [%4];"
        : "=f"(v.x), "=f"(v.y), "=f"(v.z), "=f"(v.w) : "l"(p));
    return v;
}

// ---------------- shared memory layouts ----------------
struct SmemGemm {
    float As[2][BK][BM + 4];
    float Ws[2][BK][BN + 4];
};
struct SmemPool {
    float red[8];
    float c;
    float s[8];
    int   bnd[2];
    float acc[8][F];
};
union SmemU { SmemGemm g; SmemPool p; };

// ---------------- GEMM body: C[M,N] = A[M,K] @ W[N,K]^T + bias ----------------
template <int EPI>
__device__ __forceinline__ void gemm_body(
    SmemGemm& S,
    const float* __restrict__ A, const float* __restrict__ W,
    const float* __restrict__ bias, float* __restrict__ C,
    const int* __restrict__ cnt, int N, int K, int bx, int by)
{
    const int tid  = threadIdx.x;
    const int tx   = tid % (BN / 4);
    const int ty   = tid / (BN / 4);
    const int row0 = bx * BM;
    const int col0 = by * BN;

    float4 aR, wR;
    const int r_ld  = tid / (BK / 4);
    const int c4_ld = tid % (BK / 4);

    auto ldg = [&](int k0) {
        aR = *reinterpret_cast<const float4*>(A + (size_t)(row0 + r_ld) * K + k0 + c4_ld * 4);
        wR = *reinterpret_cast<const float4*>(W + (size_t)(col0 + r_ld) * K + k0 + c4_ld * 4);
    };
    auto sts = [&](int buf) {
        S.As[buf][c4_ld * 4 + 0][r_ld] = aR.x;
        S.As[buf][c4_ld * 4 + 1][r_ld] = aR.y;
        S.As[buf][c4_ld * 4 + 2][r_ld] = aR.z;
        S.As[buf][c4_ld * 4 + 3][r_ld] = aR.w;
        S.Ws[buf][c4_ld * 4 + 0][r_ld] = wR.x;
        S.Ws[buf][c4_ld * 4 + 1][r_ld] = wR.y;
        S.Ws[buf][c4_ld * 4 + 2][r_ld] = wR.z;
        S.Ws[buf][c4_ld * 4 + 3][r_ld] = wR.w;
    };

    uint64_t acc2[4][2];
    #pragma unroll
    for (int i = 0; i < 4; ++i) { acc2[i][0] = 0ull; acc2[i][1] = 0ull; }

    const int T = K / BK;
    ldg(0);
    sts(0);
    __syncthreads();

    for (int t = 0; t < T; ++t) {
        if (t + 1 < T) ldg((t + 1) * BK);
        const int buf = t & 1;
        #pragma unroll
        for (int kk = 0; kk < BK; ++kk) {
            float4 ra = *reinterpret_cast<const float4*>(&S.As[buf][kk][ty * 4]);
            float4 rw = *reinterpret_cast<const float4*>(&S.Ws[buf][kk][tx * 4]);
            uint64_t b01 = pack2(rw.x, rw.y);
            uint64_t b23 = pack2(rw.z, rw.w);
            uint64_t a0 = bcast2(ra.x), a1 = bcast2(ra.y);
            uint64_t a2 = bcast2(ra.z), a3 = bcast2(ra.w);
            ffma2(acc2[0][0], a0, b01); ffma2(acc2[0][1], a0, b23);
            ffma2(acc2[1][0], a1, b01); ffma2(acc2[1][1], a1, b23);
            ffma2(acc2[2][0], a2, b01); ffma2(acc2[2][1], a2, b23);
            ffma2(acc2[3][0], a3, b01); ffma2(acc2[3][1], a3, b23);
        }
        if (t + 1 < T) {
            sts((t + 1) & 1);
            __syncthreads();
        }
    }

    #pragma unroll
    for (int i = 0; i < 4; ++i) {
        int r = row0 + ty * 4 + i;
        int cz = (EPI == 1) ? cnt[r] : 1;
        #pragma unroll
        for (int j = 0; j < 2; ++j) {
            int col = col0 + tx * 4 + j * 2;
            float2 v = unpack2(acc2[i][j]);
            v.x += bias[col];
            v.y += bias[col + 1];
            if (EPI == 1) {
                v.x = v.x > 0.f ? v.x : expm1f(v.x);
                v.y = v.y > 0.f ? v.y : expm1f(v.y);
                if (cz == 0) { v.x = 0.f; v.y = 0.f; }
            }
            *reinterpret_cast<float2*>(C + (size_t)r * N + col) = v;
        }
    }
}

// ---------------- binary search (segment_ids sorted) ----------------
__device__ __forceinline__ int lbound(const int* __restrict__ seg, int n, int key) {
    int lo = 0, hi = n;
    while (lo < hi) {
        int mid = (lo + hi) >> 1;
        if (__ldg(seg + mid) < key) lo = mid + 1; else hi = mid;
    }
    return lo;
}

// ---------------- fused: GH GEMM blocks + pool blocks ----------------
// Pool: unnormalized exp accumulation, coalesced lanes, unroll-4 with 8
// front-batched contiguous LDG.128, launch_bounds(256,3) — the measured-best
// load structure. ONLY change vs the 88.7us champion: the math phase uses
// fma.rn.f32x2 (16+16 FFMA2 instead of 32+32 FFMA), shortening the
// no-loads-outstanding window between load batches.
__global__ void __launch_bounds__(256, 3) fused_pool_gh_kernel(
    const float* __restrict__ nf, const float* __restrict__ gf,
    const float* __restrict__ lw, const float* __restrict__ lb,
    const float* __restrict__ whh, const float* __restrict__ bhh,
    const int* __restrict__ seg, int n_nodes)
{
    __shared__ SmemU sm;

    if (blockIdx.x < GH_BLOCKS) {
        int bx = blockIdx.x % GH_BX;
        int by = blockIdx.x / GH_BX;
        gemm_body<0>(sm.g, gf, whh, bhh, g_gh, nullptr, 3 * F, F, bx, by);
        return;
    }

    const int g    = blockIdx.x - GH_BLOCKS;
    const int tid  = threadIdx.x;
    const int warp = tid >> 5;
    const int lane = tid & 31;

    // c_g = relu(g_feats[g]) . lw[0:256] + b
    {
        float v = fmaxf(gf[g * F + tid], 0.f) * lw[tid];
        #pragma unroll
        for (int o = 16; o; o >>= 1) v += __shfl_xor_sync(0xffffffffu, v, o);
        if (lane == 0) sm.p.red[warp] = v;
    }
    if (tid == 0)  sm.p.bnd[0] = lbound(seg, n_nodes, g);
    if (tid == 32) sm.p.bnd[1] = lbound(seg, n_nodes, g + 1);
    __syncthreads();
    if (tid == 0) {
        float c = lb[0];
        #pragma unroll
        for (int w = 0; w < 8; ++w) c += sm.p.red[w];
        sm.p.c = c;
    }
    __syncthreads();
    const float c     = sm.p.c;
    const int   start = sm.p.bnd[0];
    const int   end   = sm.p.bnd[1];

    // per-lane chunks of logit_w node half (coalesced mapping),
    // both packed (main loop) and scalar (tail)
    uint64_t lwP[4];
    float lwA[4], lwB[4];
    {
        float4 a = __ldg(reinterpret_cast<const float4*>(lw + F) + lane);
        float4 b = __ldg(reinterpret_cast<const float4*>(lw + F + 128) + lane);
        lwA[0]=a.x; lwA[1]=a.y; lwA[2]=a.z; lwA[3]=a.w;
        lwB[0]=b.x; lwB[1]=b.y; lwB[2]=b.z; lwB[3]=b.w;
        lwP[0] = pack2(a.x, a.y); lwP[1] = pack2(a.z, a.w);
        lwP[2] = pack2(b.x, b.y); lwP[3] = pack2(b.z, b.w);
    }

    float s = 0.f;
    uint64_t accP[4] = {0ull, 0ull, 0ull, 0ull};

    int n = start + warp;
    // ---- main loop: 4 nodes per iteration, 8 front-batched contiguous LDG.128 ----
    for (; n + 24 < end; n += 32) {
        const float4* p = reinterpret_cast<const float4*>(nf + (size_t)n * F) + lane;
        float4 a0 = ldcs4(p),        a1 = ldcs4(p + 32);
        float4 b0 = ldcs4(p + 512),  b1 = ldcs4(p + 544);
        float4 c0 = ldcs4(p + 1024), c1 = ldcs4(p + 1056);
        float4 d0 = ldcs4(p + 1536), d1 = ldcs4(p + 1568);

        // packed dot products (16 FFMA2)
        uint64_t q1 = 0ull, q2 = 0ull, q3 = 0ull, q4 = 0ull;
        ffma2(q1, pack2(a0.x, a0.y), lwP[0]); ffma2(q2, pack2(b0.x, b0.y), lwP[0]);
        ffma2(q3, pack2(c0.x, c0.y), lwP[0]); ffma2(q4, pack2(d0.x, d0.y), lwP[0]);
        ffma2(q1, pack2(a0.z, a0.w), lwP[1]); ffma2(q2, pack2(b0.z, b0.w), lwP[1]);
        ffma2(q3, pack2(c0.z, c0.w), lwP[1]); ffma2(q4, pack2(d0.z, d0.w), lwP[1]);
        ffma2(q1, pack2(a1.x, a1.y), lwP[2]); ffma2(q2, pack2(b1.x, b1.y), lwP[2]);
        ffma2(q3, pack2(c1.x, c1.y), lwP[2]); ffma2(q4, pack2(d1.x, d1.y), lwP[2]);
        ffma2(q1, pack2(a1.z, a1.w), lwP[3]); ffma2(q2, pack2(b1.z, b1.w), lwP[3]);
        ffma2(q3, pack2(c1.z, c1.w), lwP[3]); ffma2(q4, pack2(d1.z, d1.w), lwP[3]);
        float2 u1 = unpack2(q1), u2 = unpack2(q2), u3 = unpack2(q3), u4 = unpack2(q4);
        float d1s = u1.x + u1.y, d2s = u2.x + u2.y;
        float d3s = u3.x + u3.y, d4s = u4.x + u4.y;
        #pragma unroll
        for (int o = 16; o; o >>= 1) {
            d1s += __shfl_xor_sync(0xffffffffu, d1s, o);
            d2s += __shfl_xor_sync(0xffffffffu, d2s, o);
            d3s += __shfl_xor_sync(0xffffffffu, d3s, o);
            d4s += __shfl_xor_sync(0xffffffffu, d4s, o);
        }
        float t1 = c + d1s, t2 = c + d2s, t3 = c + d3s, t4 = c + d4s;
        float z1 = t1 > 0.f ? t1 : 0.01f * t1;
        float z2 = t2 > 0.f ? t2 : 0.01f * t2;
        float z3 = t3 > 0.f ? t3 : 0.01f * t3;
        float z4 = t4 > 0.f ? t4 : 0.01f * t4;
        float e1 = __expf(z1), e2 = __expf(z2);
        float e3 = __expf(z3), e4 = __expf(z4);
        s += (e1 + e2) + (e3 + e4);
        // packed accumulation (16 FFMA2)
        uint64_t E1 = bcast2(e1), E2 = bcast2(e2), E3 = bcast2(e3), E4 = bcast2(e4);
        ffma2(accP[0], E1, pack2(a0.x, a0.y)); ffma2(accP[1], E1, pack2(a0.z, a0.w));
        ffma2(accP[2], E1, pack2(a1.x, a1.y)); ffma2(accP[3], E1, pack2(a1.z, a1.w));
        ffma2(accP[0], E2, pack2(b0.x, b0.y)); ffma2(accP[1], E2, pack2(b0.z, b0.w));
        ffma2(accP[2], E2, pack2(b1.x, b1.y)); ffma2(accP[3], E2, pack2(b1.z, b1.w));
        ffma2(accP[0], E3, pack2(c0.x, c0.y)); ffma2(accP[1], E3, pack2(c0.z, c0.w));
        ffma2(accP[2], E3, pack2(c1.x, c1.y)); ffma2(accP[3], E3, pack2(c1.z, c1.w));
        ffma2(accP[0], E4, pack2(d0.x, d0.y)); ffma2(accP[1], E4, pack2(d0.z, d0.w));
        ffma2(accP[2], E4, pack2(d1.x, d1.y)); ffma2(accP[3], E4, pack2(d1.z, d1.w));
    }
    // ---- tail: up to 3 nodes per warp ----
    for (; n < end; n += 8) {
        const float4* p = reinterpret_cast<const float4*>(nf + (size_t)n * F) + lane;
        float4 f0 = ldcs4(p), f1 = ldcs4(p + 32);
        float d = f0.x * lwA[0];
        d = fmaf(f0.y, lwA[1], d); d = fmaf(f0.z, lwA[2], d); d = fmaf(f0.w, lwA[3], d);
        d = fmaf(f1.x, lwB[0], d); d = fmaf(f1.y, lwB[1], d);
        d = fmaf(f1.z, lwB[2], d); d = fmaf(f1.w, lwB[3], d);
        #pragma unroll
        for (int o = 16; o; o >>= 1) d += __shfl_xor_sync(0xffffffffu, d, o);
        float t  = c + d;
        float z  = t > 0.f ? t : 0.01f * t;
        float e  = __expf(z);
        s += e;
        uint64_t E = bcast2(e);
        ffma2(accP[0], E, pack2(f0.x, f0.y)); ffma2(accP[1], E, pack2(f0.z, f0.w));
        ffma2(accP[2], E, pack2(f1.x, f1.y)); ffma2(accP[3], E, pack2(f1.z, f1.w));
    }

    if (lane == 0) sm.p.s[warp] = s;
    {
        float2 u;
        u = unpack2(accP[0]); sm.p.acc[warp][lane * 4 + 0] = u.x; sm.p.acc[warp][lane * 4 + 1] = u.y;
        u = unpack2(accP[1]); sm.p.acc[warp][lane * 4 + 2] = u.x; sm.p.acc[warp][lane * 4 + 3] = u.y;
        u = unpack2(accP[2]); sm.p.acc[warp][128 + lane * 4 + 0] = u.x; sm.p.acc[warp][128 + lane * 4 + 1] = u.y;
        u = unpack2(accP[3]); sm.p.acc[warp][128 + lane * 4 + 2] = u.x; sm.p.acc[warp][128 + lane * 4 + 3] = u.y;
    }
    __syncthreads();

    float S = 0.f, val = 0.f;
    #pragma unroll
    for (int w = 0; w < 8; ++w) {
        S   += sm.p.s[w];
        val += sm.p.acc[w][tid];
    }
    g_wf[g * F + tid] = (S > 0.f) ? val / S : 0.f;
    if (tid == 0) g_cnt[g] = end - start;
}

// proj: x = elu(wf @ proj_w.T + proj_b), zeroed for empty graphs
__global__ void __launch_bounds__(256) proj_kernel(
    const float* __restrict__ pw, const float* __restrict__ pb)
{
    __shared__ SmemGemm sg;
    gemm_body<1>(sg, g_wf, pw, pb, g_x, g_cnt, F, F, blockIdx.x, blockIdx.y);
}

// GI = x @ w_ih.T + b_ih  (BM=64/TM=4 gemm_body — measured best; BM=32 retile regressed)
__global__ void __launch_bounds__(256) gi_kernel(
    const float* __restrict__ wih, const float* __restrict__ bih)
{
    __shared__ SmemGemm sg;
    gemm_body<0>(sg, g_x, wih, bih, g_gi, nullptr, 3 * F, F, blockIdx.x, blockIdx.y);
}

// ---------------- GRU elementwise (float2, 512 blocks) ----------------
__global__ void __launch_bounds__(256) gru_kernel(
    const float* __restrict__ gf, float* __restrict__ out)
{
    int idx2 = blockIdx.x * blockDim.x + threadIdx.x;
    if (idx2 >= NG * F / 2) return;
    int g  = idx2 / (F / 2);
    int d2 = (idx2 % (F / 2)) * 2;
    const float* gi = g_gi + (size_t)g * 3 * F;
    const float* gh = g_gh + (size_t)g * 3 * F;

    float2 ir  = *reinterpret_cast<const float2*>(gi + d2);
    float2 iz  = *reinterpret_cast<const float2*>(gi + F + d2);
    float2 inn = *reinterpret_cast<const float2*>(gi + 2 * F + d2);
    float2 hr  = *reinterpret_cast<const float2*>(gh + d2);
    float2 hz  = *reinterpret_cast<const float2*>(gh + F + d2);
    float2 hn  = *reinterpret_cast<const float2*>(gh + 2 * F + d2);
    float2 h   = *reinterpret_cast<const float2*>(gf + (size_t)g * F + d2);

    float2 o;
    {
        float r = 0.5f * fast_tanh(0.5f * (ir.x + hr.x)) + 0.5f;
        float z = 0.5f * fast_tanh(0.5f * (iz.x + hz.x)) + 0.5f;
        float nn = fast_tanh(fmaf(r, hn.x, inn.x));
        o.x = fmaf(1.f - z, nn, z * h.x);
    }
    {
        float r = 0.5f * fast_tanh(0.5f * (ir.y + hr.y)) + 0.5f;
        float z = 0.5f * fast_tanh(0.5f * (iz.y + hz.y)) + 0.5f;
        float nn = fast_tanh(fmaf(r, hn.y, inn.y));
        o.y = fmaf(1.f - z, nn, z * h.y);
    }
    *reinterpret_cast<float2*>(out + (size_t)g * F + d2) = o;
}

// ---------------- launch ----------------
extern "C" void kernel_launch(void* const* d_in, const int* in_sizes, int n_in,
                              void* d_out, int out_size)
{
    int o = (n_in >= 12) ? 1 : 0;
    const float* nf  = (const float*)d_in[0];
    const float* gf  = (const float*)d_in[1];
    const int*   seg = (const int*)  d_in[2];
    const float* lw  = (const float*)d_in[3 + o];
    const float* lb  = (const float*)d_in[4 + o];
    const float* pw  = (const float*)d_in[5 + o];
    const float* pb  = (const float*)d_in[6 + o];
    const float* wih = (const float*)d_in[7 + o];
    const float* whh = (const float*)d_in[8 + o];
    const float* bih = (const float*)d_in[9 + o];
    const float* bhh = (const float*)d_in[10 + o];
    float* out = (float*)d_out;
    int n_nodes = in_sizes[0] / F;

    fused_pool_gh_kernel<<<GH_BLOCKS + NG, 256>>>(nf, gf, lw, lb, whh, bhh, seg, n_nodes);
    proj_kernel<<<dim3(NG / BM, F / BN), 256>>>(pw, pb);
    gi_kernel<<<dim3(NG / BM, (3 * F) / BN), 256>>>(wih, bih);
    gru_kernel<<<(NG * F / 2 + 255) / 256, 256>>>(gf, out);
}

// round 14
// speedup vs baseline: 1.0947x; 1.0740x over previous
#include <cuda_runtime.h>
#include <math.h>
#include <stdint.h>

#define F   256
#define NG  1024

// GEMM tile config (GH/proj): BM=BN=64, BK=16, TM=TN=4, 256 threads
#define BM 64
#define BN 64
#define BK 16

#define GH_BX 16                  // 1024/64
#define GH_BY 12                  // 768/64
#define GH_BLOCKS (GH_BX * GH_BY) // 192

// ---------------- scratch ----------------
__device__ float g_wf[NG * F];
__device__ int   g_cnt[NG];
__device__ float g_x[NG * F];
__device__ float g_gi[NG * 3 * F];
__device__ float g_gh[NG * 3 * F];

// ---------------- f32x2 packed-math helpers ----------------
__device__ __forceinline__ uint64_t pack2(float x, float y) {
    uint64_t r; asm("mov.b64 %0, {%1, %2};" : "=l"(r) : "f"(x), "f"(y)); return r;
}
__device__ __forceinline__ uint64_t bcast2(float x) {
    uint64_t r; asm("mov.b64 %0, {%1, %1};" : "=l"(r) : "f"(x)); return r;
}
__device__ __forceinline__ void ffma2(uint64_t& d, uint64_t a, uint64_t b) {
    asm("fma.rn.f32x2 %0, %1, %2, %0;" : "+l"(d) : "l"(a), "l"(b));
}
__device__ __forceinline__ float2 unpack2(uint64_t v) {
    float2 f; asm("mov.b64 {%0, %1}, %2;" : "=f"(f.x), "=f"(f.y) : "l"(v)); return f;
}
__device__ __forceinline__ float fast_tanh(float x) {
    float r; asm("tanh.approx.f32 %0, %1;" : "=f"(r) : "f"(x)); return r;
}
__device__ __forceinline__ float4 ldcs4(const float4* p) {
    float4 v;
    asm("ld.global.cs.v4.f32 {%0,%1,%2,%3}, [%4];"
        : "=f"(v.x), "=f"(v.y), "=f"(v.z), "=f"(v.w) : "l"(p));
    return v;
}

// ---------------- shared memory layouts ----------------
struct SmemGemm {
    float As[2][BK][BM + 4];
    float Ws[2][BK][BN + 4];
};
struct SmemPool {
    float red[8];
    float c;
    float s[8];
    int   bnd[2];
    float acc[8][F];
};
union SmemU { SmemGemm g; SmemPool p; };

// ---------------- GEMM body: C[M,N] = A[M,K] @ W[N,K]^T + bias ----------------
template <int EPI>
__device__ __forceinline__ void gemm_body(
    SmemGemm& S,
    const float* __restrict__ A, const float* __restrict__ W,
    const float* __restrict__ bias, float* __restrict__ C,
    const int* __restrict__ cnt, int N, int K, int bx, int by)
{
    const int tid  = threadIdx.x;
    const int tx   = tid % (BN / 4);
    const int ty   = tid / (BN / 4);
    const int row0 = bx * BM;
    const int col0 = by * BN;

    float4 aR, wR;
    const int r_ld  = tid / (BK / 4);
    const int c4_ld = tid % (BK / 4);

    auto ldg = [&](int k0) {
        aR = *reinterpret_cast<const float4*>(A + (size_t)(row0 + r_ld) * K + k0 + c4_ld * 4);
        wR = *reinterpret_cast<const float4*>(W + (size_t)(col0 + r_ld) * K + k0 + c4_ld * 4);
    };
    auto sts = [&](int buf) {
        S.As[buf][c4_ld * 4 + 0][r_ld] = aR.x;
        S.As[buf][c4_ld * 4 + 1][r_ld] = aR.y;
        S.As[buf][c4_ld * 4 + 2][r_ld] = aR.z;
        S.As[buf][c4_ld * 4 + 3][r_ld] = aR.w;
        S.Ws[buf][c4_ld * 4 + 0][r_ld] = wR.x;
        S.Ws[buf][c4_ld * 4 + 1][r_ld] = wR.y;
        S.Ws[buf][c4_ld * 4 + 2][r_ld] = wR.z;
        S.Ws[buf][c4_ld * 4 + 3][r_ld] = wR.w;
    };

    uint64_t acc2[4][2];
    #pragma unroll
    for (int i = 0; i < 4; ++i) { acc2[i][0] = 0ull; acc2[i][1] = 0ull; }

    const int T = K / BK;
    ldg(0);
    sts(0);
    __syncthreads();

    for (int t = 0; t < T; ++t) {
        if (t + 1 < T) ldg((t + 1) * BK);
        const int buf = t & 1;
        #pragma unroll
        for (int kk = 0; kk < BK; ++kk) {
            float4 ra = *reinterpret_cast<const float4*>(&S.As[buf][kk][ty * 4]);
            float4 rw = *reinterpret_cast<const float4*>(&S.Ws[buf][kk][tx * 4]);
            uint64_t b01 = pack2(rw.x, rw.y);
            uint64_t b23 = pack2(rw.z, rw.w);
            uint64_t a0 = bcast2(ra.x), a1 = bcast2(ra.y);
            uint64_t a2 = bcast2(ra.z), a3 = bcast2(ra.w);
            ffma2(acc2[0][0], a0, b01); ffma2(acc2[0][1], a0, b23);
            ffma2(acc2[1][0], a1, b01); ffma2(acc2[1][1], a1, b23);
            ffma2(acc2[2][0], a2, b01); ffma2(acc2[2][1], a2, b23);
            ffma2(acc2[3][0], a3, b01); ffma2(acc2[3][1], a3, b23);
        }
        if (t + 1 < T) {
            sts((t + 1) & 1);
            __syncthreads();
        }
    }

    #pragma unroll
    for (int i = 0; i < 4; ++i) {
        int r = row0 + ty * 4 + i;
        int cz = (EPI == 1) ? cnt[r] : 1;
        #pragma unroll
        for (int j = 0; j < 2; ++j) {
            int col = col0 + tx * 4 + j * 2;
            float2 v = unpack2(acc2[i][j]);
            v.x += bias[col];
            v.y += bias[col + 1];
            if (EPI == 1) {
                v.x = v.x > 0.f ? v.x : expm1f(v.x);
                v.y = v.y > 0.f ? v.y : expm1f(v.y);
                if (cz == 0) { v.x = 0.f; v.y = 0.f; }
            }
            *reinterpret_cast<float2*>(C + (size_t)r * N + col) = v;
        }
    }
}

// ---------------- binary search (segment_ids sorted) ----------------
__device__ __forceinline__ int lbound(const int* __restrict__ seg, int n, int key) {
    int lo = 0, hi = n;
    while (lo < hi) {
        int mid = (lo + hi) >> 1;
        if (__ldg(seg + mid) < key) lo = mid + 1; else hi = mid;
    }
    return lo;
}

// ---------------- fused: GH GEMM blocks + pool blocks ----------------
// Pool: unnormalized exp accumulation, coalesced lanes, unroll-4 with 8
// front-batched contiguous LDG.128, plain fmaf math, launch_bounds(256,3).
// This EXACT body measured 59.3us @ DRAM 58.8% (88.7us total) — verified
// local optimum across 5 perturbation experiments. Do not modify.
__global__ void __launch_bounds__(256, 3) fused_pool_gh_kernel(
    const float* __restrict__ nf, const float* __restrict__ gf,
    const float* __restrict__ lw, const float* __restrict__ lb,
    const float* __restrict__ whh, const float* __restrict__ bhh,
    const int* __restrict__ seg, int n_nodes)
{
    __shared__ SmemU sm;

    if (blockIdx.x < GH_BLOCKS) {
        int bx = blockIdx.x % GH_BX;
        int by = blockIdx.x / GH_BX;
        gemm_body<0>(sm.g, gf, whh, bhh, g_gh, nullptr, 3 * F, F, bx, by);
        return;
    }

    const int g    = blockIdx.x - GH_BLOCKS;
    const int tid  = threadIdx.x;
    const int warp = tid >> 5;
    const int lane = tid & 31;

    // c_g = relu(g_feats[g]) . lw[0:256] + b
    {
        float v = fmaxf(gf[g * F + tid], 0.f) * lw[tid];
        #pragma unroll
        for (int o = 16; o; o >>= 1) v += __shfl_xor_sync(0xffffffffu, v, o);
        if (lane == 0) sm.p.red[warp] = v;
    }
    if (tid == 0)  sm.p.bnd[0] = lbound(seg, n_nodes, g);
    if (tid == 32) sm.p.bnd[1] = lbound(seg, n_nodes, g + 1);
    __syncthreads();
    if (tid == 0) {
        float c = lb[0];
        #pragma unroll
        for (int w = 0; w < 8; ++w) c += sm.p.red[w];
        sm.p.c = c;
    }
    __syncthreads();
    const float c     = sm.p.c;
    const int   start = sm.p.bnd[0];
    const int   end   = sm.p.bnd[1];

    // per-lane chunks of logit_w node half (coalesced mapping)
    float lwA[4], lwB[4];
    {
        float4 a = __ldg(reinterpret_cast<const float4*>(lw + F) + lane);
        float4 b = __ldg(reinterpret_cast<const float4*>(lw + F + 128) + lane);
        lwA[0]=a.x; lwA[1]=a.y; lwA[2]=a.z; lwA[3]=a.w;
        lwB[0]=b.x; lwB[1]=b.y; lwB[2]=b.z; lwB[3]=b.w;
    }

    float s = 0.f;
    float acc[8] = {0.f, 0.f, 0.f, 0.f, 0.f, 0.f, 0.f, 0.f};

    int n = start + warp;
    // ---- main loop: 4 nodes per iteration, 8 front-batched contiguous LDG.128 ----
    for (; n + 24 < end; n += 32) {
        const float4* p = reinterpret_cast<const float4*>(nf + (size_t)n * F) + lane;
        float4 a0 = ldcs4(p),        a1 = ldcs4(p + 32);
        float4 b0 = ldcs4(p + 512),  b1 = ldcs4(p + 544);
        float4 c0 = ldcs4(p + 1024), c1 = ldcs4(p + 1056);
        float4 d0 = ldcs4(p + 1536), d1 = ldcs4(p + 1568);

        float q1 = a0.x * lwA[0], q2 = b0.x * lwA[0];
        float q3 = c0.x * lwA[0], q4 = d0.x * lwA[0];
        q1 = fmaf(a0.y, lwA[1], q1); q2 = fmaf(b0.y, lwA[1], q2);
        q3 = fmaf(c0.y, lwA[1], q3); q4 = fmaf(d0.y, lwA[1], q4);
        q1 = fmaf(a0.z, lwA[2], q1); q2 = fmaf(b0.z, lwA[2], q2);
        q3 = fmaf(c0.z, lwA[2], q3); q4 = fmaf(d0.z, lwA[2], q4);
        q1 = fmaf(a0.w, lwA[3], q1); q2 = fmaf(b0.w, lwA[3], q2);
        q3 = fmaf(c0.w, lwA[3], q3); q4 = fmaf(d0.w, lwA[3], q4);
        q1 = fmaf(a1.x, lwB[0], q1); q2 = fmaf(b1.x, lwB[0], q2);
        q3 = fmaf(c1.x, lwB[0], q3); q4 = fmaf(d1.x, lwB[0], q4);
        q1 = fmaf(a1.y, lwB[1], q1); q2 = fmaf(b1.y, lwB[1], q2);
        q3 = fmaf(c1.y, lwB[1], q3); q4 = fmaf(d1.y, lwB[1], q4);
        q1 = fmaf(a1.z, lwB[2], q1); q2 = fmaf(b1.z, lwB[2], q2);
        q3 = fmaf(c1.z, lwB[2], q3); q4 = fmaf(d1.z, lwB[2], q4);
        q1 = fmaf(a1.w, lwB[3], q1); q2 = fmaf(b1.w, lwB[3], q2);
        q3 = fmaf(c1.w, lwB[3], q3); q4 = fmaf(d1.w, lwB[3], q4);
        #pragma unroll
        for (int o = 16; o; o >>= 1) {
            q1 += __shfl_xor_sync(0xffffffffu, q1, o);
            q2 += __shfl_xor_sync(0xffffffffu, q2, o);
            q3 += __shfl_xor_sync(0xffffffffu, q3, o);
            q4 += __shfl_xor_sync(0xffffffffu, q4, o);
        }
        float t1 = c + q1, t2 = c + q2, t3 = c + q3, t4 = c + q4;
        float z1 = t1 > 0.f ? t1 : 0.01f * t1;
        float z2 = t2 > 0.f ? t2 : 0.01f * t2;
        float z3 = t3 > 0.f ? t3 : 0.01f * t3;
        float z4 = t4 > 0.f ? t4 : 0.01f * t4;
        float e1 = __expf(z1), e2 = __expf(z2);
        float e3 = __expf(z3), e4 = __expf(z4);
        s += (e1 + e2) + (e3 + e4);
        acc[0] = fmaf(e1, a0.x, fmaf(e2, b0.x, fmaf(e3, c0.x, fmaf(e4, d0.x, acc[0]))));
        acc[1] = fmaf(e1, a0.y, fmaf(e2, b0.y, fmaf(e3, c0.y, fmaf(e4, d0.y, acc[1]))));
        acc[2] = fmaf(e1, a0.z, fmaf(e2, b0.z, fmaf(e3, c0.z, fmaf(e4, d0.z, acc[2]))));
        acc[3] = fmaf(e1, a0.w, fmaf(e2, b0.w, fmaf(e3, c0.w, fmaf(e4, d0.w, acc[3]))));
        acc[4] = fmaf(e1, a1.x, fmaf(e2, b1.x, fmaf(e3, c1.x, fmaf(e4, d1.x, acc[4]))));
        acc[5] = fmaf(e1, a1.y, fmaf(e2, b1.y, fmaf(e3, c1.y, fmaf(e4, d1.y, acc[5]))));
        acc[6] = fmaf(e1, a1.z, fmaf(e2, b1.z, fmaf(e3, c1.z, fmaf(e4, d1.z, acc[6]))));
        acc[7] = fmaf(e1, a1.w, fmaf(e2, b1.w, fmaf(e3, c1.w, fmaf(e4, d1.w, acc[7]))));
    }
    // ---- tail: up to 3 nodes per warp ----
    for (; n < end; n += 8) {
        const float4* p = reinterpret_cast<const float4*>(nf + (size_t)n * F) + lane;
        float4 f0 = ldcs4(p), f1 = ldcs4(p + 32);
        float d = f0.x * lwA[0];
        d = fmaf(f0.y, lwA[1], d); d = fmaf(f0.z, lwA[2], d); d = fmaf(f0.w, lwA[3], d);
        d = fmaf(f1.x, lwB[0], d); d = fmaf(f1.y, lwB[1], d);
        d = fmaf(f1.z, lwB[2], d); d = fmaf(f1.w, lwB[3], d);
        #pragma unroll
        for (int o = 16; o; o >>= 1) d += __shfl_xor_sync(0xffffffffu, d, o);
        float t  = c + d;
        float z  = t > 0.f ? t : 0.01f * t;
        float e  = __expf(z);
        s += e;
        acc[0] = fmaf(e, f0.x, acc[0]);
        acc[1] = fmaf(e, f0.y, acc[1]);
        acc[2] = fmaf(e, f0.z, acc[2]);
        acc[3] = fmaf(e, f0.w, acc[3]);
        acc[4] = fmaf(e, f1.x, acc[4]);
        acc[5] = fmaf(e, f1.y, acc[5]);
        acc[6] = fmaf(e, f1.z, acc[6]);
        acc[7] = fmaf(e, f1.w, acc[7]);
    }

    if (lane == 0) sm.p.s[warp] = s;
    #pragma unroll
    for (int j = 0; j < 4; ++j) {
        sm.p.acc[warp][lane * 4 + j]       = acc[j];
        sm.p.acc[warp][128 + lane * 4 + j] = acc[4 + j];
    }
    __syncthreads();

    float S = 0.f, val = 0.f;
    #pragma unroll
    for (int w = 0; w < 8; ++w) {
        S   += sm.p.s[w];
        val += sm.p.acc[w][tid];
    }
    g_wf[g * F + tid] = (S > 0.f) ? val / S : 0.f;
    if (tid == 0) g_cnt[g] = end - start;
}

// proj: x = elu(wf @ proj_w.T + proj_b), zeroed for empty graphs
__global__ void __launch_bounds__(256) proj_kernel(
    const float* __restrict__ pw, const float* __restrict__ pb)
{
    __shared__ SmemGemm sg;
    gemm_body<1>(sg, g_wf, pw, pb, g_x, g_cnt, F, F, blockIdx.x, blockIdx.y);
}

// ---------------- GI = x @ w_ih.T + b_ih ----------------
// BM=32, BN=64, TM=TN=4 (ratio identical to champion tile), 128 threads.
// 384 blocks of 128 threads — same total warps as the 192x256 config, but
// 2.6 blocks/SM so another block issues during each block's sync/LDG stalls.
__global__ void __launch_bounds__(128) gi_kernel(
    const float* __restrict__ wih, const float* __restrict__ bih)
{
    __shared__ float As[2][16][36];
    __shared__ float Ws[2][16][68];

    const int tid  = threadIdx.x;        // 0..127
    const int tx   = tid & 15;           // cols tx*4 .. tx*4+3  (64)
    const int ty   = tid >> 4;           // rows ty*4 .. ty*4+3  (32)
    const int row0 = blockIdx.x * 32;
    const int col0 = blockIdx.y * 64;

    const int lr  = tid >> 2;            // 0..31
    const int lc4 = tid & 3;             // 0..3

    float4 aR, wR0, wR1;
    auto ldg = [&](int k0) {
        aR  = *reinterpret_cast<const float4*>(g_x + (size_t)(row0 + lr) * F + k0 + lc4 * 4);
        wR0 = *reinterpret_cast<const float4*>(wih + (size_t)(col0 + lr) * F + k0 + lc4 * 4);
        wR1 = *reinterpret_cast<const float4*>(wih + (size_t)(col0 + 32 + lr) * F + k0 + lc4 * 4);
    };
    auto sts = [&](int buf) {
        As[buf][lc4 * 4 + 0][lr] = aR.x;
        As[buf][lc4 * 4 + 1][lr] = aR.y;
        As[buf][lc4 * 4 + 2][lr] = aR.z;
        As[buf][lc4 * 4 + 3][lr] = aR.w;
        Ws[buf][lc4 * 4 + 0][lr] = wR0.x;
        Ws[buf][lc4 * 4 + 1][lr] = wR0.y;
        Ws[buf][lc4 * 4 + 2][lr] = wR0.z;
        Ws[buf][lc4 * 4 + 3][lr] = wR0.w;
        Ws[buf][lc4 * 4 + 0][32 + lr] = wR1.x;
        Ws[buf][lc4 * 4 + 1][32 + lr] = wR1.y;
        Ws[buf][lc4 * 4 + 2][32 + lr] = wR1.z;
        Ws[buf][lc4 * 4 + 3][32 + lr] = wR1.w;
    };

    uint64_t acc2[4][2];
    #pragma unroll
    for (int i = 0; i < 4; ++i) { acc2[i][0] = 0ull; acc2[i][1] = 0ull; }

    ldg(0); sts(0); __syncthreads();
    for (int t = 0; t < 16; ++t) {
        if (t + 1 < 16) ldg((t + 1) * 16);
        const int buf = t & 1;
        #pragma unroll
        for (int kk = 0; kk < 16; ++kk) {
            float4 ra = *reinterpret_cast<const float4*>(&As[buf][kk][ty * 4]);
            float4 rw = *reinterpret_cast<const float4*>(&Ws[buf][kk][tx * 4]);
            uint64_t b01 = pack2(rw.x, rw.y);
            uint64_t b23 = pack2(rw.z, rw.w);
            uint64_t a0 = bcast2(ra.x), a1 = bcast2(ra.y);
            uint64_t a2 = bcast2(ra.z), a3 = bcast2(ra.w);
            ffma2(acc2[0][0], a0, b01); ffma2(acc2[0][1], a0, b23);
            ffma2(acc2[1][0], a1, b01); ffma2(acc2[1][1], a1, b23);
            ffma2(acc2[2][0], a2, b01); ffma2(acc2[2][1], a2, b23);
            ffma2(acc2[3][0], a3, b01); ffma2(acc2[3][1], a3, b23);
        }
        if (t + 1 < 16) { sts((t + 1) & 1); __syncthreads(); }
    }

    #pragma unroll
    for (int i = 0; i < 4; ++i) {
        int r = row0 + ty * 4 + i;
        #pragma unroll
        for (int j = 0; j < 2; ++j) {
            int col = col0 + tx * 4 + j * 2;
            float2 v = unpack2(acc2[i][j]);
            v.x += bih[col];
            v.y += bih[col + 1];
            *reinterpret_cast<float2*>(g_gi + (size_t)r * (3 * F) + col) = v;
        }
    }
}

// ---------------- GRU elementwise (float2, 512 blocks) ----------------
__global__ void __launch_bounds__(256) gru_kernel(
    const float* __restrict__ gf, float* __restrict__ out)
{
    int idx2 = blockIdx.x * blockDim.x + threadIdx.x;
    if (idx2 >= NG * F / 2) return;
    int g  = idx2 / (F / 2);
    int d2 = (idx2 % (F / 2)) * 2;
    const float* gi = g_gi + (size_t)g * 3 * F;
    const float* gh = g_gh + (size_t)g * 3 * F;

    float2 ir  = *reinterpret_cast<const float2*>(gi + d2);
    float2 iz  = *reinterpret_cast<const float2*>(gi + F + d2);
    float2 inn = *reinterpret_cast<const float2*>(gi + 2 * F + d2);
    float2 hr  = *reinterpret_cast<const float2*>(gh + d2);
    float2 hz  = *reinterpret_cast<const float2*>(gh + F + d2);
    float2 hn  = *reinterpret_cast<const float2*>(gh + 2 * F + d2);
    float2 h   = *reinterpret_cast<const float2*>(gf + (size_t)g * F + d2);

    float2 o;
    {
        float r = 0.5f * fast_tanh(0.5f * (ir.x + hr.x)) + 0.5f;
        float z = 0.5f * fast_tanh(0.5f * (iz.x + hz.x)) + 0.5f;
        float nn = fast_tanh(fmaf(r, hn.x, inn.x));
        o.x = fmaf(1.f - z, nn, z * h.x);
    }
    {
        float r = 0.5f * fast_tanh(0.5f * (ir.y + hr.y)) + 0.5f;
        float z = 0.5f * fast_tanh(0.5f * (iz.y + hz.y)) + 0.5f;
        float nn = fast_tanh(fmaf(r, hn.y, inn.y));
        o.y = fmaf(1.f - z, nn, z * h.y);
    }
    *reinterpret_cast<float2*>(out + (size_t)g * F + d2) = o;
}

// ---------------- launch ----------------
extern "C" void kernel_launch(void* const* d_in, const int* in_sizes, int n_in,
                              void* d_out, int out_size)
{
    int o = (n_in >= 12) ? 1 : 0;
    const float* nf  = (const float*)d_in[0];
    const float* gf  = (const float*)d_in[1];
    const int*   seg = (const int*)  d_in[2];
    const float* lw  = (const float*)d_in[3 + o];
    const float* lb  = (const float*)d_in[4 + o];
    const float* pw  = (const float*)d_in[5 + o];
    const float* pb  = (const float*)d_in[6 + o];
    const float* wih = (const float*)d_in[7 + o];
    const float* whh = (const float*)d_in[8 + o];
    const float* bih = (const float*)d_in[9 + o];
    const float* bhh = (const float*)d_in[10 + o];
    float* out = (float*)d_out;
    int n_nodes = in_sizes[0] / F;

    fused_pool_gh_kernel<<<GH_BLOCKS + NG, 256>>>(nf, gf, lw, lb, whh, bhh, seg, n_nodes);
    proj_kernel<<<dim3(NG / BM, F / BN), 256>>>(pw, pb);
    gi_kernel<<<dim3(NG / 32, (3 * F) / 64), 128>>>(wih, bih);
    gru_kernel<<<(NG * F / 2 + 255) / 256, 256>>>(gf, out);
}

// round 15
// speedup vs baseline: 1.1272x; 1.0297x over previous
#include <cuda_runtime.h>
#include <math.h>
#include <stdint.h>

#define F   256
#define NG  1024

// GEMM tile config (GH): BM=BN=64, BK=16, TM=TN=4, 256 threads
#define BM 64
#define BN 64
#define BK 16

#define GH_BX 16                  // 1024/64
#define GH_BY 12                  // 768/64
#define GH_BLOCKS (GH_BX * GH_BY) // 192

// ---------------- scratch ----------------
__device__ float g_wf[NG * F];
__device__ int   g_cnt[NG];
__device__ float g_x[NG * F];
__device__ float g_gi[NG * 3 * F];
__device__ float g_gh[NG * 3 * F];

// ---------------- f32x2 packed-math helpers ----------------
__device__ __forceinline__ uint64_t pack2(float x, float y) {
    uint64_t r; asm("mov.b64 %0, {%1, %2};" : "=l"(r) : "f"(x), "f"(y)); return r;
}
__device__ __forceinline__ uint64_t bcast2(float x) {
    uint64_t r; asm("mov.b64 %0, {%1, %1};" : "=l"(r) : "f"(x)); return r;
}
__device__ __forceinline__ void ffma2(uint64_t& d, uint64_t a, uint64_t b) {
    asm("fma.rn.f32x2 %0, %1, %2, %0;" : "+l"(d) : "l"(a), "l"(b));
}
__device__ __forceinline__ float2 unpack2(uint64_t v) {
    float2 f; asm("mov.b64 {%0, %1}, %2;" : "=f"(f.x), "=f"(f.y) : "l"(v)); return f;
}
__device__ __forceinline__ float fast_tanh(float x) {
    float r; asm("tanh.approx.f32 %0, %1;" : "=f"(r) : "f"(x)); return r;
}
__device__ __forceinline__ float4 ldcs4(const float4* p) {
    float4 v;
    asm("ld.global.cs.v4.f32 {%0,%1,%2,%3}, [%4];"
        : "=f"(v.x), "=f"(v.y), "=f"(v.z), "=f"(v.w) : "l"(p));
    return v;
}

// ---------------- shared memory layouts ----------------
struct SmemGemm {
    float As[2][BK][BM + 4];
    float Ws[2][BK][BN + 4];
};
struct SmemPool {
    float red[8];
    float c;
    float s[8];
    int   bnd[2];
    float acc[8][F];
};
union SmemU { SmemGemm g; SmemPool p; };

// ---------------- GEMM body (256 threads, BM=BN=64): used by GH ----------------
template <int EPI>
__device__ __forceinline__ void gemm_body(
    SmemGemm& S,
    const float* __restrict__ A, const float* __restrict__ W,
    const float* __restrict__ bias, float* __restrict__ C,
    const int* __restrict__ cnt, int N, int K, int bx, int by)
{
    const int tid  = threadIdx.x;
    const int tx   = tid % (BN / 4);
    const int ty   = tid / (BN / 4);
    const int row0 = bx * BM;
    const int col0 = by * BN;

    float4 aR, wR;
    const int r_ld  = tid / (BK / 4);
    const int c4_ld = tid % (BK / 4);

    auto ldg = [&](int k0) {
        aR = *reinterpret_cast<const float4*>(A + (size_t)(row0 + r_ld) * K + k0 + c4_ld * 4);
        wR = *reinterpret_cast<const float4*>(W + (size_t)(col0 + r_ld) * K + k0 + c4_ld * 4);
    };
    auto sts = [&](int buf) {
        S.As[buf][c4_ld * 4 + 0][r_ld] = aR.x;
        S.As[buf][c4_ld * 4 + 1][r_ld] = aR.y;
        S.As[buf][c4_ld * 4 + 2][r_ld] = aR.z;
        S.As[buf][c4_ld * 4 + 3][r_ld] = aR.w;
        S.Ws[buf][c4_ld * 4 + 0][r_ld] = wR.x;
        S.Ws[buf][c4_ld * 4 + 1][r_ld] = wR.y;
        S.Ws[buf][c4_ld * 4 + 2][r_ld] = wR.z;
        S.Ws[buf][c4_ld * 4 + 3][r_ld] = wR.w;
    };

    uint64_t acc2[4][2];
    #pragma unroll
    for (int i = 0; i < 4; ++i) { acc2[i][0] = 0ull; acc2[i][1] = 0ull; }

    const int T = K / BK;
    ldg(0);
    sts(0);
    __syncthreads();

    for (int t = 0; t < T; ++t) {
        if (t + 1 < T) ldg((t + 1) * BK);
        const int buf = t & 1;
        #pragma unroll
        for (int kk = 0; kk < BK; ++kk) {
            float4 ra = *reinterpret_cast<const float4*>(&S.As[buf][kk][ty * 4]);
            float4 rw = *reinterpret_cast<const float4*>(&S.Ws[buf][kk][tx * 4]);
            uint64_t b01 = pack2(rw.x, rw.y);
            uint64_t b23 = pack2(rw.z, rw.w);
            uint64_t a0 = bcast2(ra.x), a1 = bcast2(ra.y);
            uint64_t a2 = bcast2(ra.z), a3 = bcast2(ra.w);
            ffma2(acc2[0][0], a0, b01); ffma2(acc2[0][1], a0, b23);
            ffma2(acc2[1][0], a1, b01); ffma2(acc2[1][1], a1, b23);
            ffma2(acc2[2][0], a2, b01); ffma2(acc2[2][1], a2, b23);
            ffma2(acc2[3][0], a3, b01); ffma2(acc2[3][1], a3, b23);
        }
        if (t + 1 < T) {
            sts((t + 1) & 1);
            __syncthreads();
        }
    }

    #pragma unroll
    for (int i = 0; i < 4; ++i) {
        int r = row0 + ty * 4 + i;
        int cz = (EPI == 1) ? cnt[r] : 1;
        #pragma unroll
        for (int j = 0; j < 2; ++j) {
            int col = col0 + tx * 4 + j * 2;
            float2 v = unpack2(acc2[i][j]);
            v.x += bias[col];
            v.y += bias[col + 1];
            if (EPI == 1) {
                v.x = v.x > 0.f ? v.x : expm1f(v.x);
                v.y = v.y > 0.f ? v.y : expm1f(v.y);
                if (cz == 0) { v.x = 0.f; v.y = 0.f; }
            }
            *reinterpret_cast<float2*>(C + (size_t)r * N + col) = v;
        }
    }
}

// ---------------- small GEMM body (128 threads, BM=32, BN=64, TM=TN=4) ------
// Same per-thread tile as the champion, smaller block -> more blocks/SM.
// Used by proj (EPI=1) and gi (EPI=0).
template <int EPI>
__device__ __forceinline__ void gemm_body_128(
    const float* __restrict__ A, const float* __restrict__ W,
    const float* __restrict__ bias, float* __restrict__ C,
    const int* __restrict__ cnt, int N, int K, int bx, int by)
{
    __shared__ float As[2][16][36];
    __shared__ float Ws[2][16][68];

    const int tid  = threadIdx.x;        // 0..127
    const int tx   = tid & 15;           // cols tx*4 .. tx*4+3  (64)
    const int ty   = tid >> 4;           // rows ty*4 .. ty*4+3  (32)
    const int row0 = bx * 32;
    const int col0 = by * 64;

    const int lr  = tid >> 2;            // 0..31
    const int lc4 = tid & 3;             // 0..3

    float4 aR, wR0, wR1;
    auto ldg = [&](int k0) {
        aR  = *reinterpret_cast<const float4*>(A + (size_t)(row0 + lr) * K + k0 + lc4 * 4);
        wR0 = *reinterpret_cast<const float4*>(W + (size_t)(col0 + lr) * K + k0 + lc4 * 4);
        wR1 = *reinterpret_cast<const float4*>(W + (size_t)(col0 + 32 + lr) * K + k0 + lc4 * 4);
    };
    auto sts = [&](int buf) {
        As[buf][lc4 * 4 + 0][lr] = aR.x;
        As[buf][lc4 * 4 + 1][lr] = aR.y;
        As[buf][lc4 * 4 + 2][lr] = aR.z;
        As[buf][lc4 * 4 + 3][lr] = aR.w;
        Ws[buf][lc4 * 4 + 0][lr] = wR0.x;
        Ws[buf][lc4 * 4 + 1][lr] = wR0.y;
        Ws[buf][lc4 * 4 + 2][lr] = wR0.z;
        Ws[buf][lc4 * 4 + 3][lr] = wR0.w;
        Ws[buf][lc4 * 4 + 0][32 + lr] = wR1.x;
        Ws[buf][lc4 * 4 + 1][32 + lr] = wR1.y;
        Ws[buf][lc4 * 4 + 2][32 + lr] = wR1.z;
        Ws[buf][lc4 * 4 + 3][32 + lr] = wR1.w;
    };

    uint64_t acc2[4][2];
    #pragma unroll
    for (int i = 0; i < 4; ++i) { acc2[i][0] = 0ull; acc2[i][1] = 0ull; }

    const int T = K / 16;
    ldg(0); sts(0); __syncthreads();
    for (int t = 0; t < T; ++t) {
        if (t + 1 < T) ldg((t + 1) * 16);
        const int buf = t & 1;
        #pragma unroll
        for (int kk = 0; kk < 16; ++kk) {
            float4 ra = *reinterpret_cast<const float4*>(&As[buf][kk][ty * 4]);
            float4 rw = *reinterpret_cast<const float4*>(&Ws[buf][kk][tx * 4]);
            uint64_t b01 = pack2(rw.x, rw.y);
            uint64_t b23 = pack2(rw.z, rw.w);
            uint64_t a0 = bcast2(ra.x), a1 = bcast2(ra.y);
            uint64_t a2 = bcast2(ra.z), a3 = bcast2(ra.w);
            ffma2(acc2[0][0], a0, b01); ffma2(acc2[0][1], a0, b23);
            ffma2(acc2[1][0], a1, b01); ffma2(acc2[1][1], a1, b23);
            ffma2(acc2[2][0], a2, b01); ffma2(acc2[2][1], a2, b23);
            ffma2(acc2[3][0], a3, b01); ffma2(acc2[3][1], a3, b23);
        }
        if (t + 1 < T) { sts((t + 1) & 1); __syncthreads(); }
    }

    #pragma unroll
    for (int i = 0; i < 4; ++i) {
        int r = row0 + ty * 4 + i;
        int cz = (EPI == 1) ? cnt[r] : 1;
        #pragma unroll
        for (int j = 0; j < 2; ++j) {
            int col = col0 + tx * 4 + j * 2;
            float2 v = unpack2(acc2[i][j]);
            v.x += bias[col];
            v.y += bias[col + 1];
            if (EPI == 1) {
                v.x = v.x > 0.f ? v.x : expm1f(v.x);
                v.y = v.y > 0.f ? v.y : expm1f(v.y);
                if (cz == 0) { v.x = 0.f; v.y = 0.f; }
            }
            *reinterpret_cast<float2*>(C + (size_t)r * N + col) = v;
        }
    }
}

// ---------------- binary search (segment_ids sorted) ----------------
__device__ __forceinline__ int lbound(const int* __restrict__ seg, int n, int key) {
    int lo = 0, hi = n;
    while (lo < hi) {
        int mid = (lo + hi) >> 1;
        if (__ldg(seg + mid) < key) lo = mid + 1; else hi = mid;
    }
    return lo;
}

// ---------------- fused: GH GEMM blocks + pool blocks ----------------
// Pool: unnormalized exp accumulation, coalesced lanes, unroll-4 with 8
// front-batched contiguous LDG.128, plain fmaf math, launch_bounds(256,3).
// Verified local optimum (59.3us @ DRAM 58.8%). Do not modify.
__global__ void __launch_bounds__(256, 3) fused_pool_gh_kernel(
    const float* __restrict__ nf, const float* __restrict__ gf,
    const float* __restrict__ lw, const float* __restrict__ lb,
    const float* __restrict__ whh, const float* __restrict__ bhh,
    const int* __restrict__ seg, int n_nodes)
{
    __shared__ SmemU sm;

    if (blockIdx.x < GH_BLOCKS) {
        int bx = blockIdx.x % GH_BX;
        int by = blockIdx.x / GH_BX;
        gemm_body<0>(sm.g, gf, whh, bhh, g_gh, nullptr, 3 * F, F, bx, by);
        return;
    }

    const int g    = blockIdx.x - GH_BLOCKS;
    const int tid  = threadIdx.x;
    const int warp = tid >> 5;
    const int lane = tid & 31;

    // c_g = relu(g_feats[g]) . lw[0:256] + b
    {
        float v = fmaxf(gf[g * F + tid], 0.f) * lw[tid];
        #pragma unroll
        for (int o = 16; o; o >>= 1) v += __shfl_xor_sync(0xffffffffu, v, o);
        if (lane == 0) sm.p.red[warp] = v;
    }
    if (tid == 0)  sm.p.bnd[0] = lbound(seg, n_nodes, g);
    if (tid == 32) sm.p.bnd[1] = lbound(seg, n_nodes, g + 1);
    __syncthreads();
    if (tid == 0) {
        float c = lb[0];
        #pragma unroll
        for (int w = 0; w < 8; ++w) c += sm.p.red[w];
        sm.p.c = c;
    }
    __syncthreads();
    const float c     = sm.p.c;
    const int   start = sm.p.bnd[0];
    const int   end   = sm.p.bnd[1];

    // per-lane chunks of logit_w node half (coalesced mapping)
    float lwA[4], lwB[4];
    {
        float4 a = __ldg(reinterpret_cast<const float4*>(lw + F) + lane);
        float4 b = __ldg(reinterpret_cast<const float4*>(lw + F + 128) + lane);
        lwA[0]=a.x; lwA[1]=a.y; lwA[2]=a.z; lwA[3]=a.w;
        lwB[0]=b.x; lwB[1]=b.y; lwB[2]=b.z; lwB[3]=b.w;
    }

    float s = 0.f;
    float acc[8] = {0.f, 0.f, 0.f, 0.f, 0.f, 0.f, 0.f, 0.f};

    int n = start + warp;
    // ---- main loop: 4 nodes per iteration, 8 front-batched contiguous LDG.128 ----
    for (; n + 24 < end; n += 32) {
        const float4* p = reinterpret_cast<const float4*>(nf + (size_t)n * F) + lane;
        float4 a0 = ldcs4(p),        a1 = ldcs4(p + 32);
        float4 b0 = ldcs4(p + 512),  b1 = ldcs4(p + 544);
        float4 c0 = ldcs4(p + 1024), c1 = ldcs4(p + 1056);
        float4 d0 = ldcs4(p + 1536), d1 = ldcs4(p + 1568);

        float q1 = a0.x * lwA[0], q2 = b0.x * lwA[0];
        float q3 = c0.x * lwA[0], q4 = d0.x * lwA[0];
        q1 = fmaf(a0.y, lwA[1], q1); q2 = fmaf(b0.y, lwA[1], q2);
        q3 = fmaf(c0.y, lwA[1], q3); q4 = fmaf(d0.y, lwA[1], q4);
        q1 = fmaf(a0.z, lwA[2], q1); q2 = fmaf(b0.z, lwA[2], q2);
        q3 = fmaf(c0.z, lwA[2], q3); q4 = fmaf(d0.z, lwA[2], q4);
        q1 = fmaf(a0.w, lwA[3], q1); q2 = fmaf(b0.w, lwA[3], q2);
        q3 = fmaf(c0.w, lwA[3], q3); q4 = fmaf(d0.w, lwA[3], q4);
        q1 = fmaf(a1.x, lwB[0], q1); q2 = fmaf(b1.x, lwB[0], q2);
        q3 = fmaf(c1.x, lwB[0], q3); q4 = fmaf(d1.x, lwB[0], q4);
        q1 = fmaf(a1.y, lwB[1], q1); q2 = fmaf(b1.y, lwB[1], q2);
        q3 = fmaf(c1.y, lwB[1], q3); q4 = fmaf(d1.y, lwB[1], q4);
        q1 = fmaf(a1.z, lwB[2], q1); q2 = fmaf(b1.z, lwB[2], q2);
        q3 = fmaf(c1.z, lwB[2], q3); q4 = fmaf(d1.z, lwB[2], q4);
        q1 = fmaf(a1.w, lwB[3], q1); q2 = fmaf(b1.w, lwB[3], q2);
        q3 = fmaf(c1.w, lwB[3], q3); q4 = fmaf(d1.w, lwB[3], q4);
        #pragma unroll
        for (int o = 16; o; o >>= 1) {
            q1 += __shfl_xor_sync(0xffffffffu, q1, o);
            q2 += __shfl_xor_sync(0xffffffffu, q2, o);
            q3 += __shfl_xor_sync(0xffffffffu, q3, o);
            q4 += __shfl_xor_sync(0xffffffffu, q4, o);
        }
        float t1 = c + q1, t2 = c + q2, t3 = c + q3, t4 = c + q4;
        float z1 = t1 > 0.f ? t1 : 0.01f * t1;
        float z2 = t2 > 0.f ? t2 : 0.01f * t2;
        float z3 = t3 > 0.f ? t3 : 0.01f * t3;
        float z4 = t4 > 0.f ? t4 : 0.01f * t4;
        float e1 = __expf(z1), e2 = __expf(z2);
        float e3 = __expf(z3), e4 = __expf(z4);
        s += (e1 + e2) + (e3 + e4);
        acc[0] = fmaf(e1, a0.x, fmaf(e2, b0.x, fmaf(e3, c0.x, fmaf(e4, d0.x, acc[0]))));
        acc[1] = fmaf(e1, a0.y, fmaf(e2, b0.y, fmaf(e3, c0.y, fmaf(e4, d0.y, acc[1]))));
        acc[2] = fmaf(e1, a0.z, fmaf(e2, b0.z, fmaf(e3, c0.z, fmaf(e4, d0.z, acc[2]))));
        acc[3] = fmaf(e1, a0.w, fmaf(e2, b0.w, fmaf(e3, c0.w, fmaf(e4, d0.w, acc[3]))));
        acc[4] = fmaf(e1, a1.x, fmaf(e2, b1.x, fmaf(e3, c1.x, fmaf(e4, d1.x, acc[4]))));
        acc[5] = fmaf(e1, a1.y, fmaf(e2, b1.y, fmaf(e3, c1.y, fmaf(e4, d1.y, acc[5]))));
        acc[6] = fmaf(e1, a1.z, fmaf(e2, b1.z, fmaf(e3, c1.z, fmaf(e4, d1.z, acc[6]))));
        acc[7] = fmaf(e1, a1.w, fmaf(e2, b1.w, fmaf(e3, c1.w, fmaf(e4, d1.w, acc[7]))));
    }
    // ---- tail: up to 3 nodes per warp ----
    for (; n < end; n += 8) {
        const float4* p = reinterpret_cast<const float4*>(nf + (size_t)n * F) + lane;
        float4 f0 = ldcs4(p), f1 = ldcs4(p + 32);
        float d = f0.x * lwA[0];
        d = fmaf(f0.y, lwA[1], d); d = fmaf(f0.z, lwA[2], d); d = fmaf(f0.w, lwA[3], d);
        d = fmaf(f1.x, lwB[0], d); d = fmaf(f1.y, lwB[1], d);
        d = fmaf(f1.z, lwB[2], d); d = fmaf(f1.w, lwB[3], d);
        #pragma unroll
        for (int o = 16; o; o >>= 1) d += __shfl_xor_sync(0xffffffffu, d, o);
        float t  = c + d;
        float z  = t > 0.f ? t : 0.01f * t;
        float e  = __expf(z);
        s += e;
        acc[0] = fmaf(e, f0.x, acc[0]);
        acc[1] = fmaf(e, f0.y, acc[1]);
        acc[2] = fmaf(e, f0.z, acc[2]);
        acc[3] = fmaf(e, f0.w, acc[3]);
        acc[4] = fmaf(e, f1.x, acc[4]);
        acc[5] = fmaf(e, f1.y, acc[5]);
        acc[6] = fmaf(e, f1.z, acc[6]);
        acc[7] = fmaf(e, f1.w, acc[7]);
    }

    if (lane == 0) sm.p.s[warp] = s;
    #pragma unroll
    for (int j = 0; j < 4; ++j) {
        sm.p.acc[warp][lane * 4 + j]       = acc[j];
        sm.p.acc[warp][128 + lane * 4 + j] = acc[4 + j];
    }
    __syncthreads();

    float S = 0.f, val = 0.f;
    #pragma unroll
    for (int w = 0; w < 8; ++w) {
        S   += sm.p.s[w];
        val += sm.p.acc[w][tid];
    }
    g_wf[g * F + tid] = (S > 0.f) ? val / S : 0.f;
    if (tid == 0) g_cnt[g] = end - start;
}

// proj: x = elu(wf @ proj_w.T + proj_b), zeroed for empty graphs
// 128-thread small-tile body -> 128 blocks (was 64x256 = 0.43 blocks/SM)
__global__ void __launch_bounds__(128) proj_kernel(
    const float* __restrict__ pw, const float* __restrict__ pb)
{
    gemm_body_128<1>(g_wf, pw, pb, g_x, g_cnt, F, F, blockIdx.x, blockIdx.y);
}

// GI = x @ w_ih.T + b_ih  (384 blocks x 128 threads — round-14 win)
__global__ void __launch_bounds__(128) gi_kernel(
    const float* __restrict__ wih, const float* __restrict__ bih)
{
    gemm_body_128<0>(g_x, wih, bih, g_gi, nullptr, 3 * F, F, blockIdx.x, blockIdx.y);
}

// ---------------- GRU elementwise (float2, 512 blocks) ----------------
__global__ void __launch_bounds__(256) gru_kernel(
    const float* __restrict__ gf, float* __restrict__ out)
{
    int idx2 = blockIdx.x * blockDim.x + threadIdx.x;
    if (idx2 >= NG * F / 2) return;
    int g  = idx2 / (F / 2);
    int d2 = (idx2 % (F / 2)) * 2;
    const float* gi = g_gi + (size_t)g * 3 * F;
    const float* gh = g_gh + (size_t)g * 3 * F;

    float2 ir  = *reinterpret_cast<const float2*>(gi + d2);
    float2 iz  = *reinterpret_cast<const float2*>(gi + F + d2);
    float2 inn = *reinterpret_cast<const float2*>(gi + 2 * F + d2);
    float2 hr  = *reinterpret_cast<const float2*>(gh + d2);
    float2 hz  = *reinterpret_cast<const float2*>(gh + F + d2);
    float2 hn  = *reinterpret_cast<const float2*>(gh + 2 * F + d2);
    float2 h   = *reinterpret_cast<const float2*>(gf + (size_t)g * F + d2);

    float2 o;
    {
        float r = 0.5f * fast_tanh(0.5f * (ir.x + hr.x)) + 0.5f;
        float z = 0.5f * fast_tanh(0.5f * (iz.x + hz.x)) + 0.5f;
        float nn = fast_tanh(fmaf(r, hn.x, inn.x));
        o.x = fmaf(1.f - z, nn, z * h.x);
    }
    {
        float r = 0.5f * fast_tanh(0.5f * (ir.y + hr.y)) + 0.5f;
        float z = 0.5f * fast_tanh(0.5f * (iz.y + hz.y)) + 0.5f;
        float nn = fast_tanh(fmaf(r, hn.y, inn.y));
        o.y = fmaf(1.f - z, nn, z * h.y);
    }
    *reinterpret_cast<float2*>(out + (size_t)g * F + d2) = o;
}

// ---------------- launch ----------------
extern "C" void kernel_launch(void* const* d_in, const int* in_sizes, int n_in,
                              void* d_out, int out_size)
{
    int o = (n_in >= 12) ? 1 : 0;
    const float* nf  = (const float*)d_in[0];
    const float* gf  = (const float*)d_in[1];
    const int*   seg = (const int*)  d_in[2];
    const float* lw  = (const float*)d_in[3 + o];
    const float* lb  = (const float*)d_in[4 + o];
    const float* pw  = (const float*)d_in[5 + o];
    const float* pb  = (const float*)d_in[6 + o];
    const float* wih = (const float*)d_in[7 + o];
    const float* whh = (const float*)d_in[8 + o];
    const float* bih = (const float*)d_in[9 + o];
    const float* bhh = (const float*)d_in[10 + o];
    float* out = (float*)d_out;
    int n_nodes = in_sizes[0] / F;

    fused_pool_gh_kernel<<<GH_BLOCKS + NG, 256>>>(nf, gf, lw, lb, whh, bhh, seg, n_nodes);
    proj_kernel<<<dim3(NG / 32, F / 64), 128>>>(pw, pb);
    gi_kernel<<<dim3(NG / 32, (3 * F) / 64), 128>>>(wih, bih);
    gru_kernel<<<(NG * F / 2 + 255) / 256, 256>>>(gf, out);
}